// round 14
// baseline (speedup 1.0000x reference)
#include <cuda_runtime.h>
#include <cuda_bf16.h>
#include <math.h>
#include <stdint.h>

#define T 2048
#define HID 2048
#define HQ 32
#define G 2
#define D 64
#define HG 16          // HQ / G
#define C_NUM 127      // compressed windows
#define TOPK 16
#define WINDOW 512
#define SCALE 0.125f

// ------------------------- scratch (device globals; no allocs) --------------
__device__ float g_q[T * HQ * D];
__device__ float g_k[T * G * D];
__device__ float g_v[T * G * D];
__device__ float g_gate[T * 3];
__device__ float g_psum[G * T * 128];
__device__ unsigned g_sel[G * T];
__device__ float g_att[T * HQ * D];
__device__ float g_cos[T * 32];
__device__ float g_sin[T * 32];

// bf16 split buffers
__device__ __align__(16) __nv_bfloat16 g_xh[T * HID];
__device__ __align__(16) __nv_bfloat16 g_xl[T * HID];
__device__ __align__(16) __nv_bfloat16 g_wqh[HQ * D * HID];
__device__ __align__(16) __nv_bfloat16 g_wql[HQ * D * HID];
__device__ __align__(16) __nv_bfloat16 g_wkh[G * D * HID];
__device__ __align__(16) __nv_bfloat16 g_wkl[G * D * HID];
__device__ __align__(16) __nv_bfloat16 g_wvh[G * D * HID];
__device__ __align__(16) __nv_bfloat16 g_wvl[G * D * HID];
__device__ __align__(16) __nv_bfloat16 g_woh[HID * HID];
__device__ __align__(16) __nv_bfloat16 g_wol[HID * HID];
__device__ __align__(16) __nv_bfloat16 g_ath[T * HID];
__device__ __align__(16) __nv_bfloat16 g_atl[T * HID];
// attention K/V bf16 hi/lo, FRAGMENT-PERMUTED layouts
__device__ __align__(16) __nv_bfloat16 g_kh[T * G * D];
__device__ __align__(16) __nv_bfloat16 g_kl[T * G * D];
__device__ __align__(16) __nv_bfloat16 g_vth[G * D * T];
__device__ __align__(16) __nv_bfloat16 g_vtl[G * D * T];
// compressed K / V^T, fragment-permuted bf16 hi/lo (zero-init pads)
__device__ __align__(16) __nv_bfloat16 g_ckh[G * 128 * 64];
__device__ __align__(16) __nv_bfloat16 g_ckl[G * 128 * 64];
__device__ __align__(16) __nv_bfloat16 g_cvth[G * 64 * 128];
__device__ __align__(16) __nv_bfloat16 g_cvtl[G * 64 * 128];

// ------------------------- helpers ------------------------------------------
__device__ __forceinline__ void split2(float x, float y, unsigned& h,
                                       unsigned& l) {
    __nv_bfloat162 hh = __floats2bfloat162_rn(x, y);
    float hx = __bfloat162float(__low2bfloat16(hh));
    float hy = __bfloat162float(__high2bfloat16(hh));
    __nv_bfloat162 ll = __floats2bfloat162_rn(x - hx, y - hy);
    h = *reinterpret_cast<unsigned*>(&hh);
    l = *reinterpret_cast<unsigned*>(&ll);
}

__device__ __forceinline__ int frag_perm(int o) {
    return ((o & 3) << 3) + ((o >> 3) << 1) + ((o >> 2) & 1);
}

// ------------------------- fp32 -> bf16 hi/lo split --------------------------
__global__ void split_kernel(const float* __restrict__ src,
                             __nv_bfloat16* __restrict__ hi,
                             __nv_bfloat16* __restrict__ lo, int n) {
    int i = (blockIdx.x * blockDim.x + threadIdx.x) * 4;
    if (i >= n) return;
    float4 v = *(const float4*)(src + i);
    unsigned h0, l0, h1, l1;
    split2(v.x, v.y, h0, l0);
    split2(v.z, v.w, h1, l1);
    ((unsigned*)(hi + i))[0] = h0;
    ((unsigned*)(hi + i))[1] = h1;
    ((unsigned*)(lo + i))[0] = l0;
    ((unsigned*)(lo + i))[1] = l1;
}

// K split (permuted d) + V transpose/split (permuted t within 64-block)
__global__ void kvsplit_kernel() {
    int i = blockIdx.x * blockDim.x + threadIdx.x;  // over T*G*D
    int d = i & 63;
    float kv = g_k[i];
    __nv_bfloat16 h = __float2bfloat16(kv);
    int nd = (frag_perm(d >> 1) << 1) + (d & 1);
    g_kh[(i - d) + nd] = h;
    g_kl[(i - d) + nd] = __float2bfloat16(kv - __bfloat162float(h));

    int t = i >> 7, gd = i & 127;
    float vv = g_v[i];
    __nv_bfloat16 vh = __float2bfloat16(vv);
    int tt = t & 63;
    int nt = (t & ~63) + (frag_perm(tt >> 1) << 1) + (tt & 1);
    int o = gd * T + nt;
    g_vth[o] = vh;
    g_vtl[o] = __float2bfloat16(vv - __bfloat162float(vh));
}

// ------------------------- MMA macros ----------------------------------------
#define SMS 40
#define ARR_BYTES 10240           // 128 rows x 40 bf16 x 2B
#define STAGE_B (4 * ARR_BYTES)   // Ah,Al,Bh,Bl
#define GEMM_SMEM2 (2 * STAGE_B)  // 80 KB

#define LDSM4(r0, r1, r2, r3, addr)                                       \
    asm volatile("ldmatrix.sync.aligned.m8n8.x4.shared.b16 "              \
                 "{%0,%1,%2,%3}, [%4];"                                   \
                 : "=r"(r0), "=r"(r1), "=r"(r2), "=r"(r3) : "r"(addr))

#define MMA_BF16(dd, aa, bb)                                              \
    asm volatile("mma.sync.aligned.m16n8k16.row.col.f32.bf16.bf16.f32 "   \
                 "{%0,%1,%2,%3},{%4,%5,%6,%7},{%8,%9},{%0,%1,%2,%3};"     \
                 : "+f"(dd[0]), "+f"(dd[1]), "+f"(dd[2]), "+f"(dd[3])     \
                 : "r"(aa[0]), "r"(aa[1]), "r"(aa[2]), "r"(aa[3]),        \
                   "r"(bb[0]), "r"(bb[1]))

__device__ __forceinline__ void cp16(unsigned dst, const void* src) {
    asm volatile("cp.async.cg.shared.global [%0], [%1], 16;" ::"r"(dst),
                 "l"(src));
}
#define CP_COMMIT() asm volatile("cp.async.commit_group;")

// cp.async 2-stage double-buffered bf16x3 GEMM core, 2 CTAs/SM
__device__ __forceinline__ void gemm_core(
    const __nv_bfloat16* __restrict__ Ah, const __nv_bfloat16* __restrict__ Al,
    const __nv_bfloat16* __restrict__ Bh, const __nv_bfloat16* __restrict__ Bl,
    float* __restrict__ C, int ldc, int bm, int bnw, int bnc, int K) {
    extern __shared__ __align__(16) char dsm[];

    int tid = threadIdx.x;
    int lrow = tid >> 1, lcol = (tid & 1) << 4;
    int wid = tid >> 5, lane = tid & 31;
    int wm = wid & 1, wn = wid >> 1;
    int m0 = wm * 64, n0 = wn * 32;
    int g8 = lane >> 2, tig = lane & 3;

    const __nv_bfloat16* pAh = Ah + (size_t)(bm + lrow) * K + lcol;
    const __nv_bfloat16* pAl = Al + (size_t)(bm + lrow) * K + lcol;
    const __nv_bfloat16* pBh = Bh + (size_t)(bnw + lrow) * K + lcol;
    const __nv_bfloat16* pBl = Bl + (size_t)(bnw + lrow) * K + lcol;

    float acc[4][4][4];
#pragma unroll
    for (int i = 0; i < 4; i++)
#pragma unroll
        for (int j = 0; j < 4; j++)
#pragma unroll
            for (int r = 0; r < 4; r++) acc[i][j][r] = 0.f;

    int aoff = (m0 + (lane & 7) + ((lane >> 3) & 1) * 8) * SMS + (lane >> 4) * 8;
    int boff = (n0 + (lane & 7) + (lane >> 4) * 8) * SMS + ((lane >> 3) & 1) * 8;
    unsigned sbase = (unsigned)__cvta_generic_to_shared(dsm);
    unsigned sidx = (unsigned)((lrow * SMS + lcol) * 2);

    int niter = K / 32;
#pragma unroll
    for (int s = 0; s < 2; s++) {
        unsigned o = sbase + s * STAGE_B + sidx;
        int k0 = s * 32;
        cp16(o, pAh + k0);
        cp16(o + 16, pAh + k0 + 8);
        cp16(o + ARR_BYTES, pAl + k0);
        cp16(o + ARR_BYTES + 16, pAl + k0 + 8);
        cp16(o + 2 * ARR_BYTES, pBh + k0);
        cp16(o + 2 * ARR_BYTES + 16, pBh + k0 + 8);
        cp16(o + 3 * ARR_BYTES, pBl + k0);
        cp16(o + 3 * ARR_BYTES + 16, pBl + k0 + 8);
        CP_COMMIT();
    }

    for (int it = 0; it < niter; it++) {
        asm volatile("cp.async.wait_group 1;");
        __syncthreads();
        unsigned cb = sbase + (it & 1) * STAGE_B;
        unsigned uAh = cb, uAl = cb + ARR_BYTES;
        unsigned uBh = cb + 2 * ARR_BYTES, uBl = cb + 3 * ARR_BYTES;
#pragma unroll
        for (int kk = 0; kk < 32; kk += 16) {
            unsigned bh[4][2], bl[4][2];
#pragma unroll
            for (int j2 = 0; j2 < 2; j2++) {
                unsigned bd = (unsigned)((boff + j2 * 16 * SMS + kk) * 2);
                LDSM4(bh[2 * j2][0], bh[2 * j2][1], bh[2 * j2 + 1][0],
                      bh[2 * j2 + 1][1], uBh + bd);
                LDSM4(bl[2 * j2][0], bl[2 * j2][1], bl[2 * j2 + 1][0],
                      bl[2 * j2 + 1][1], uBl + bd);
            }
#pragma unroll
            for (int i = 0; i < 4; i++) {
                unsigned ah[4], al[4];
                unsigned ad = (unsigned)((aoff + i * 16 * SMS + kk) * 2);
                LDSM4(ah[0], ah[1], ah[2], ah[3], uAh + ad);
                LDSM4(al[0], al[1], al[2], al[3], uAl + ad);
#pragma unroll
                for (int j = 0; j < 4; j++) {
                    MMA_BF16(acc[i][j], ah, bh[j]);
                    MMA_BF16(acc[i][j], ah, bl[j]);
                    MMA_BF16(acc[i][j], al, bh[j]);
                }
            }
        }
        __syncthreads();
        if (it + 2 < niter) {
            unsigned o = cb + sidx;
            int k0 = (it + 2) * 32;
            cp16(o, pAh + k0);
            cp16(o + 16, pAh + k0 + 8);
            cp16(o + ARR_BYTES, pAl + k0);
            cp16(o + ARR_BYTES + 16, pAl + k0 + 8);
            cp16(o + 2 * ARR_BYTES, pBh + k0);
            cp16(o + 2 * ARR_BYTES + 16, pBh + k0 + 8);
            cp16(o + 3 * ARR_BYTES, pBl + k0);
            cp16(o + 3 * ARR_BYTES + 16, pBl + k0 + 8);
        }
        CP_COMMIT();
    }
#pragma unroll
    for (int i = 0; i < 4; i++) {
        int r0 = bm + m0 + i * 16 + g8;
#pragma unroll
        for (int j = 0; j < 4; j++) {
            int col = bnc + n0 + j * 8 + tig * 2;
            *(float2*)(C + (size_t)r0 * ldc + col) =
                make_float2(acc[i][j][0], acc[i][j][1]);
            *(float2*)(C + (size_t)(r0 + 8) * ldc + col) =
                make_float2(acc[i][j][2], acc[i][j][3]);
        }
    }
}

// ------------------------- QKV fused GEMM ------------------------------------
__global__ __launch_bounds__(256, 2) void gemm_qkv() {
    int bx = blockIdx.x;
    const __nv_bfloat16 *Bh, *Bl;
    float* C;
    int ldc, bnw, bnc;
    if (bx < 16) {
        Bh = g_wqh; Bl = g_wql; C = g_q; ldc = HQ * D;
        bnw = bx * 128; bnc = bx * 128;
    } else if (bx == 16) {
        Bh = g_wkh; Bl = g_wkl; C = g_k; ldc = G * D; bnw = 0; bnc = 0;
    } else {
        Bh = g_wvh; Bl = g_wvl; C = g_v; ldc = G * D; bnw = 0; bnc = 0;
    }
    gemm_core(g_xh, g_xl, Bh, Bl, C, ldc, blockIdx.y * 128, bnw, bnc, HID);
}

// ------------------------- Wo GEMM --------------------------------------------
__global__ __launch_bounds__(256, 2) void gemm_out(float* __restrict__ C) {
    gemm_core(g_ath, g_atl, g_woh, g_wol, C, HID, blockIdx.y * 128,
              blockIdx.x * 128, blockIdx.x * 128, HID);
}

// ------------------------- gate = x @ Wgate^T --------------------------------
__global__ void gate_kernel(const float* __restrict__ x,
                            const float* __restrict__ Wg) {
    int t = blockIdx.x;
    int w = threadIdx.x >> 5, lane = threadIdx.x & 31;
    const float* xr = x + (size_t)t * HID;
    const float* wr = Wg + (size_t)w * HID;
    float acc = 0.f;
    for (int i = lane; i < HID; i += 32) acc += xr[i] * wr[i];
#pragma unroll
    for (int off = 16; off; off >>= 1)
        acc += __shfl_xor_sync(0xffffffffu, acc, off);
    if (!lane) g_gate[t * 3 + w] = acc;
}

// ------------------------- RoPE: table + apply --------------------------------
__global__ void rope_table_kernel() {
    int t = blockIdx.x, d = threadIdx.x;
    double inv = exp(-(double)d * (log(10000.0) / 32.0));
    double sn, cs;
    sincos((double)t * inv, &sn, &cs);
    g_cos[t * 32 + d] = (float)cs;
    g_sin[t * 32 + d] = (float)sn;
}

__global__ void rope_apply_kernel(float* x, int nh) {
    int t = blockIdx.x;
    for (int idx = threadIdx.x; idx < nh * 32; idx += blockDim.x) {
        int hh = idx >> 5, d = idx & 31;
        float cs = g_cos[t * 32 + d], sn = g_sin[t * 32 + d];
        float* p = x + ((size_t)t * nh + hh) * D;
        float x1 = p[d], x2 = p[d + 32];
        p[d]      = x1 * cs - x2 * sn;
        p[d + 32] = x2 * cs + x1 * sn;
    }
}

// ------------------------- compression -> fragment-permuted bf16 -------------
__global__ __launch_bounds__(256) void compress_kernel(
    const float* __restrict__ Wck, const float* __restrict__ Wcv) {
    int c = blockIdx.x, g = blockIdx.y, which = blockIdx.z;
    const float* src = which ? g_v : g_k;
    const float* W = (which ? Wcv : Wck) + (size_t)g * 2048 * D;
    __shared__ float win[32 * 64];
    __shared__ float partial[4][64];
    int tid = threadIdx.x;
    for (int i = tid; i < 2048; i += 256) {
        int j = i >> 6, dd = i & 63;
        win[i] = src[((size_t)(16 * c + j) * G + g) * D + dd];
    }
    __syncthreads();
    int d = tid & 63, q = tid >> 6;
    float acc = 0.f;
    const float* Wp = W + (size_t)(q * 512) * D + d;
    const float* wp = win + q * 512;
#pragma unroll 8
    for (int f = 0; f < 512; f++) acc += wp[f] * Wp[(size_t)f * D];
    partial[q][d] = acc;
    __syncthreads();
    if (tid < 64) {
        float val = partial[0][tid] + partial[1][tid] + partial[2][tid] +
                    partial[3][tid];
        __nv_bfloat16 h = __float2bfloat16(val);
        __nv_bfloat16 lo = __float2bfloat16(val - __bfloat162float(h));
        if (which == 0) {
            int nd = (frag_perm(tid >> 1) << 1) + (tid & 1);
            size_t o = ((size_t)g * 128 + c) * 64 + nd;
            g_ckh[o] = h;
            g_ckl[o] = lo;
        } else {
            int pc = (c & ~63) + (frag_perm((c & 63) >> 1) << 1) + (c & 1);
            size_t o = ((size_t)g * 64 + tid) * 128 + pc;
            g_cvth[o] = h;
            g_cvtl[o] = lo;
        }
    }
}

// ------------------------- compressed attention (MMA) + psum -----------------
__global__ __launch_bounds__(256) void comp_attn_kernel() {
    int t = blockIdx.x, g = blockIdx.y;
    int tid = threadIdx.x;
    int warp = tid >> 5, lane = tid & 31;
    int g8 = lane >> 2, tig = lane & 3;
    int h = tid >> 4, m16 = tid & 15;

    __shared__ float sS[16][128];
    __shared__ float sp[16][128];

    int nc = (t >= 31) ? ((t - 31) >> 4) + 1 : 0;
    float gate0 = 1.f / (1.f + expf(-g_gate[t * 3 + 0]));
    float* psum_out = g_psum + ((size_t)g * T + t) * 128;
    float* out = g_att + ((size_t)t * HQ + g * HG) * D;

    if (nc == 0) {
        int d0 = m16 << 2;
        *(float4*)(out + h * D + d0) = make_float4(0.f, 0.f, 0.f, 0.f);
        if (tid < 128) psum_out[tid] = 0.f;
        return;
    }

    // q fragments hi/lo, pre-scaled by SCALE
    unsigned aqh[4][4], aql[4][4];
    {
        const float* qbase = g_q + ((size_t)t * HQ + g * HG) * D;
#pragma unroll
        for (int c = 0; c < 4; c++) {
            int d0 = c * 16 + 2 * tig;
            float2 v00 = *(const float2*)(qbase + g8 * D + d0);
            float2 v10 = *(const float2*)(qbase + (g8 + 8) * D + d0);
            float2 v01 = *(const float2*)(qbase + g8 * D + d0 + 8);
            float2 v11 = *(const float2*)(qbase + (g8 + 8) * D + d0 + 8);
            split2(v00.x * SCALE, v00.y * SCALE, aqh[c][0], aql[c][0]);
            split2(v10.x * SCALE, v10.y * SCALE, aqh[c][1], aql[c][1]);
            split2(v01.x * SCALE, v01.y * SCALE, aqh[c][2], aql[c][2]);
            split2(v11.x * SCALE, v11.y * SCALE, aqh[c][3], aql[c][3]);
        }
    }

    {
#pragma unroll
        for (int j = 0; j < 2; j++) {
            float S[4] = {0.f, 0.f, 0.f, 0.f};
            int crow = 16 * warp + 8 * j + g8;
            size_t rowoff = ((size_t)g * 128 + crow) * 64;
            const uint4* ph = (const uint4*)(g_ckh + rowoff) + tig * 2;
            const uint4* pl = (const uint4*)(g_ckl + rowoff) + tig * 2;
            uint4 H0 = ph[0], H1 = ph[1];
            uint4 L0 = pl[0], L1 = pl[1];
            unsigned bh[4][2] = {{H0.x, H0.y}, {H0.z, H0.w},
                                 {H1.x, H1.y}, {H1.z, H1.w}};
            unsigned bl[4][2] = {{L0.x, L0.y}, {L0.z, L0.w},
                                 {L1.x, L1.y}, {L1.z, L1.w}};
#pragma unroll
            for (int c4 = 0; c4 < 4; c4++) {
                MMA_BF16(S, aqh[c4], bh[c4]);
                MMA_BF16(S, aql[c4], bh[c4]);
                MMA_BF16(S, aqh[c4], bl[c4]);
            }
            int cc = 16 * warp + 8 * j + 2 * tig;
            sS[g8][cc] = S[0];
            sS[g8][cc + 1] = S[1];
            sS[g8 + 8][cc] = S[2];
            sS[g8 + 8][cc + 1] = S[3];
        }
    }
    __syncthreads();

    {
        float sv[8];
        float mx = -INFINITY;
#pragma unroll
        for (int r = 0; r < 8; r++) {
            int c = r * 16 + m16;
            float v = (c < nc) ? sS[h][c] : -INFINITY;
            sv[r] = v;
            mx = fmaxf(mx, v);
        }
#pragma unroll
        for (int off = 8; off; off >>= 1)
            mx = fmaxf(mx, __shfl_xor_sync(0xffffffffu, mx, off, 16));
        float l = 0.f;
#pragma unroll
        for (int r = 0; r < 8; r++) {
            sv[r] = __expf(sv[r] - mx);
            l += sv[r];
        }
#pragma unroll
        for (int off = 8; off; off >>= 1)
            l += __shfl_xor_sync(0xffffffffu, l, off, 16);
        float invl = 1.f / l;
#pragma unroll
        for (int r = 0; r < 8; r++) sp[h][r * 16 + m16] = sv[r] * invl;
    }
    __syncthreads();

    if (tid < 128) {
        float s = 0.f;
        if (tid < nc) {
#pragma unroll
            for (int hh = 0; hh < HG; hh++) s += sp[hh][tid];
        }
        psum_out[tid] = s;
    }

    float acc[4] = {0.f, 0.f, 0.f, 0.f};
#pragma unroll
    for (int b64 = 0; b64 < 2; b64++) {
        size_t rowoff = ((size_t)g * 64 + 8 * warp + g8) * 128 + 64 * b64;
        const uint4* pvh = (const uint4*)(g_cvth + rowoff) + tig * 2;
        const uint4* pvl = (const uint4*)(g_cvtl + rowoff) + tig * 2;
        uint4 H0 = pvh[0], H1 = pvh[1];
        uint4 L0 = pvl[0], L1 = pvl[1];
        unsigned bh[4][2] = {{H0.x, H0.y}, {H0.z, H0.w},
                             {H1.x, H1.y}, {H1.z, H1.w}};
        unsigned bl[4][2] = {{L0.x, L0.y}, {L0.z, L0.w},
                             {L1.x, L1.y}, {L1.z, L1.w}};
#pragma unroll
        for (int kcl = 0; kcl < 4; kcl++) {
            int kc = 4 * b64 + kcl;
            float2 p00 = *(const float2*)&sp[g8][16 * kc + 2 * tig];
            float2 p10 = *(const float2*)&sp[g8 + 8][16 * kc + 2 * tig];
            float2 p01 = *(const float2*)&sp[g8][16 * kc + 8 + 2 * tig];
            float2 p11 = *(const float2*)&sp[g8 + 8][16 * kc + 8 + 2 * tig];
            unsigned ah[4], al[4];
            split2(p00.x, p00.y, ah[0], al[0]);
            split2(p10.x, p10.y, ah[1], al[1]);
            split2(p01.x, p01.y, ah[2], al[2]);
            split2(p11.x, p11.y, ah[3], al[3]);
            MMA_BF16(acc, ah, bh[kcl]);
            MMA_BF16(acc, al, bh[kcl]);
            MMA_BF16(acc, ah, bl[kcl]);
        }
    }
    int dcol = 8 * warp + 2 * tig;
    out[g8 * D + dcol] = gate0 * acc[0];
    out[g8 * D + dcol + 1] = gate0 * acc[1];
    out[(g8 + 8) * D + dcol] = gate0 * acc[2];
    out[(g8 + 8) * D + dcol + 1] = gate0 * acc[3];
}

// ------------------------- block score + stable top-k ------------------------
__global__ void select_kernel() {
    int t = blockIdx.x, g = blockIdx.y;
    int b = threadIdx.x;
    const float* ps = g_psum + ((size_t)g * T + t) * 128;
    float sc = 0.f;
    int clo = 4 * b - 1; if (clo < 0) clo = 0;
    int chi = 4 * b + 3; if (chi > C_NUM - 1) chi = C_NUM - 1;
    for (int c = clo; c <= chi; c++) sc += ps[c];
    int qb = t >> 6;
    bool causal = (b <= qb);
    bool forced = (b < 1) || ((qb - b < 2) && causal);
    float val = causal ? (forced ? INFINITY : sc) : -INFINITY;
    unsigned selbits = 0;
    for (int it = 0; it < TOPK; it++) {
        float rv = val; int ri = b;
#pragma unroll
        for (int off = 16; off; off >>= 1) {
            float ov = __shfl_xor_sync(0xffffffffu, rv, off);
            int oi = __shfl_xor_sync(0xffffffffu, ri, off);
            if (ov > rv || (ov == rv && oi < ri)) { rv = ov; ri = oi; }
        }
        if (rv == -INFINITY) break;
        selbits |= (1u << ri);
        if (b == ri) val = -INFINITY;
    }
    if (b == 0) g_sel[(size_t)g * T + t] = selbits;
}

// ------------------------- merged MMA flash attention ------------------------
// Union-block schedule; QK once per block; single PV pass feeding both
// branch accumulators (V loaded once).
__global__ __launch_bounds__(256) void attn_mma_kernel() {
    int t = blockIdx.x, g = blockIdx.y;
    int tid = threadIdx.x;
    int warp = tid >> 5, lane = tid & 31;
    int g8 = lane >> 2, tig = lane & 3;

    __shared__ float sm_m[8][16];
    __shared__ float sm_l[8][16];
    __shared__ float sacc[8][16][64];

    int qb = t >> 6;
    int lo = t - WINDOW; if (lo < 0) lo = 0;
    unsigned msel = g_sel[(size_t)g * T + t];
    unsigned mwin = ((2u << qb) - 1) & ~((1u << (lo >> 6)) - 1);
    unsigned mall = msel | mwin;

    // q fragments hi/lo, pre-scaled by SCALE
    unsigned aqh[4][4], aql[4][4];
    {
        const float* qbase = g_q + ((size_t)t * HQ + g * HG) * D;
#pragma unroll
        for (int c = 0; c < 4; c++) {
            int d0 = c * 16 + 2 * tig;
            float2 v00 = *(const float2*)(qbase + g8 * D + d0);
            float2 v10 = *(const float2*)(qbase + (g8 + 8) * D + d0);
            float2 v01 = *(const float2*)(qbase + g8 * D + d0 + 8);
            float2 v11 = *(const float2*)(qbase + (g8 + 8) * D + d0 + 8);
            split2(v00.x * SCALE, v00.y * SCALE, aqh[c][0], aql[c][0]);
            split2(v10.x * SCALE, v10.y * SCALE, aqh[c][1], aql[c][1]);
            split2(v01.x * SCALE, v01.y * SCALE, aqh[c][2], aql[c][2]);
            split2(v11.x * SCALE, v11.y * SCALE, aqh[c][3], aql[c][3]);
        }
    }

    float m1a = -INFINITY, m1b = -INFINITY, l1a = 0.f, l1b = 0.f;
    float m2a = -INFINITY, m2b = -INFINITY, l2a = 0.f, l2b = 0.f;
    float acc1[8][4], acc2[8][4];
#pragma unroll
    for (int j = 0; j < 8; j++)
#pragma unroll
        for (int r = 0; r < 4; r++) { acc1[j][r] = 0.f; acc2[j][r] = 0.f; }

    unsigned rem = mall;
    int bidx = 0;
    while (rem) {
        int b = __ffs(rem) - 1;
        rem &= rem - 1;
        if ((bidx++ & 7) != warp) continue;
        int sbase = b << 6;
        int smax = t - sbase; if (smax > 63) smax = 63;
        bool act1 = (msel >> b) & 1u;
        bool act2 = (mwin >> b) & 1u;
        int smin2 = lo - sbase; if (smin2 < 0) smin2 = 0;

        // ----- QK once (q pre-scaled) -----
        float S[8][4];
#pragma unroll
        for (int j = 0; j < 8; j++)
#pragma unroll
            for (int r = 0; r < 4; r++) S[j][r] = 0.f;
#pragma unroll
        for (int j = 0; j < 8; j++) {
            size_t rowoff = ((size_t)(sbase + 8 * j + g8) * G + g) * D;
            const uint4* ph = (const uint4*)(g_kh + rowoff) + tig * 2;
            const uint4* pl = (const uint4*)(g_kl + rowoff) + tig * 2;
            uint4 H0 = ph[0], H1 = ph[1];
            uint4 L0 = pl[0], L1 = pl[1];
            unsigned bh[4][2] = {{H0.x, H0.y}, {H0.z, H0.w},
                                 {H1.x, H1.y}, {H1.z, H1.w}};
            unsigned bl[4][2] = {{L0.x, L0.y}, {L0.z, L0.w},
                                 {L1.x, L1.y}, {L1.z, L1.w}};
#pragma unroll
            for (int c = 0; c < 4; c++) {
                MMA_BF16(S[j], aqh[c], bh[c]);
                MMA_BF16(S[j], aql[c], bh[c]);
                MMA_BF16(S[j], aqh[c], bl[c]);
            }
        }

        int soff = 2 * tig;
        unsigned p1h0[8], p1h1[8], p1l0[8], p1l1[8];
        unsigned p2h0[8], p2h1[8], p2l0[8], p2l1[8];

        // ----- branch 1 softmax update (smin = 0) -----
        if (act1) {
            float bmax0 = -INFINITY, bmax1 = -INFINITY;
#pragma unroll
            for (int j = 0; j < 8; j++) {
                int s0i = 8 * j + soff, s1i = s0i + 1;
                if (s0i <= smax) {
                    bmax0 = fmaxf(bmax0, S[j][0]);
                    bmax1 = fmaxf(bmax1, S[j][2]);
                }
                if (s1i <= smax) {
                    bmax0 = fmaxf(bmax0, S[j][1]);
                    bmax1 = fmaxf(bmax1, S[j][3]);
                }
            }
            bmax0 = fmaxf(bmax0, __shfl_xor_sync(0xffffffffu, bmax0, 1));
            bmax0 = fmaxf(bmax0, __shfl_xor_sync(0xffffffffu, bmax0, 2));
            bmax1 = fmaxf(bmax1, __shfl_xor_sync(0xffffffffu, bmax1, 1));
            bmax1 = fmaxf(bmax1, __shfl_xor_sync(0xffffffffu, bmax1, 2));
            float mn0 = fmaxf(m1a, bmax0), mn1 = fmaxf(m1b, bmax1);
            float cor0 = __expf(m1a - mn0), cor1 = __expf(m1b - mn1);
            m1a = mn0; m1b = mn1;

            float ps0 = 0.f, ps1 = 0.f;
#pragma unroll
            for (int j = 0; j < 8; j++) {
                int s0i = 8 * j + soff, s1i = s0i + 1;
                float p0 = (s0i <= smax) ? __expf(S[j][0] - mn0) : 0.f;
                float p1 = (s1i <= smax) ? __expf(S[j][1] - mn0) : 0.f;
                float p2 = (s0i <= smax) ? __expf(S[j][2] - mn1) : 0.f;
                float p3 = (s1i <= smax) ? __expf(S[j][3] - mn1) : 0.f;
                ps0 += p0 + p1;
                ps1 += p2 + p3;
                split2(p0, p1, p1h0[j], p1l0[j]);
                split2(p2, p3, p1h1[j], p1l1[j]);
            }
            ps0 += __shfl_xor_sync(0xffffffffu, ps0, 1);
            ps0 += __shfl_xor_sync(0xffffffffu, ps0, 2);
            ps1 += __shfl_xor_sync(0xffffffffu, ps1, 1);
            ps1 += __shfl_xor_sync(0xffffffffu, ps1, 2);
            l1a = l1a * cor0 + ps0;
            l1b = l1b * cor1 + ps1;
#pragma unroll
            for (int j = 0; j < 8; j++) {
                acc1[j][0] *= cor0; acc1[j][1] *= cor0;
                acc1[j][2] *= cor1; acc1[j][3] *= cor1;
            }
        }

        // ----- branch 2 softmax update (window [smin2, smax]) -----
        if (act2) {
            float bmax0 = -INFINITY, bmax1 = -INFINITY;
#pragma unroll
            for (int j = 0; j < 8; j++) {
                int s0i = 8 * j + soff, s1i = s0i + 1;
                if (s0i >= smin2 && s0i <= smax) {
                    bmax0 = fmaxf(bmax0, S[j][0]);
                    bmax1 = fmaxf(bmax1, S[j][2]);
                }
                if (s1i >= smin2 && s1i <= smax) {
                    bmax0 = fmaxf(bmax0, S[j][1]);
                    bmax1 = fmaxf(bmax1, S[j][3]);
                }
            }
            bmax0 = fmaxf(bmax0, __shfl_xor_sync(0xffffffffu, bmax0, 1));
            bmax0 = fmaxf(bmax0, __shfl_xor_sync(0xffffffffu, bmax0, 2));
            bmax1 = fmaxf(bmax1, __shfl_xor_sync(0xffffffffu, bmax1, 1));
            bmax1 = fmaxf(bmax1, __shfl_xor_sync(0xffffffffu, bmax1, 2));
            float mn0 = fmaxf(m2a, bmax0), mn1 = fmaxf(m2b, bmax1);
            float cor0 = __expf(m2a - mn0), cor1 = __expf(m2b - mn1);
            m2a = mn0; m2b = mn1;

            float ps0 = 0.f, ps1 = 0.f;
#pragma unroll
            for (int j = 0; j < 8; j++) {
                int s0i = 8 * j + soff, s1i = s0i + 1;
                bool v0 = (s0i >= smin2) && (s0i <= smax);
                bool v1 = (s1i >= smin2) && (s1i <= smax);
                float p0 = v0 ? __expf(S[j][0] - mn0) : 0.f;
                float p1 = v1 ? __expf(S[j][1] - mn0) : 0.f;
                float p2 = v0 ? __expf(S[j][2] - mn1) : 0.f;
                float p3 = v1 ? __expf(S[j][3] - mn1) : 0.f;
                ps0 += p0 + p1;
                ps1 += p2 + p3;
                split2(p0, p1, p2h0[j], p2l0[j]);
                split2(p2, p3, p2h1[j], p2l1[j]);
            }
            ps0 += __shfl_xor_sync(0xffffffffu, ps0, 1);
            ps0 += __shfl_xor_sync(0xffffffffu, ps0, 2);
            ps1 += __shfl_xor_sync(0xffffffffu, ps1, 1);
            ps1 += __shfl_xor_sync(0xffffffffu, ps1, 2);
            l2a = l2a * cor0 + ps0;
            l2b = l2b * cor1 + ps1;
#pragma unroll
            for (int j = 0; j < 8; j++) {
                acc2[j][0] *= cor0; acc2[j][1] *= cor0;
                acc2[j][2] *= cor1; acc2[j][3] *= cor1;
            }
        }

        // ----- single PV pass: V loaded once, feeds both branches -----
#pragma unroll
        for (int jd = 0; jd < 8; jd++) {
            size_t rowoff = ((size_t)(g * D + g8 + 8 * jd)) * T + sbase;
            const uint4* pvh = (const uint4*)(g_vth + rowoff) + tig * 2;
            const uint4* pvl = (const uint4*)(g_vtl + rowoff) + tig * 2;
            uint4 H0 = pvh[0], H1 = pvh[1];
            uint4 L0 = pvl[0], L1 = pvl[1];
            unsigned bh[4][2] = {{H0.x, H0.y}, {H0.z, H0.w},
                                 {H1.x, H1.y}, {H1.z, H1.w}};
            unsigned bl[4][2] = {{L0.x, L0.y}, {L0.z, L0.w},
                                 {L1.x, L1.y}, {L1.z, L1.w}};
            if (act1) {
#pragma unroll
                for (int kc = 0; kc < 4; kc++) {
                    unsigned ah[4] = {p1h0[2 * kc], p1h1[2 * kc],
                                      p1h0[2 * kc + 1], p1h1[2 * kc + 1]};
                    unsigned al_[4] = {p1l0[2 * kc], p1l1[2 * kc],
                                       p1l0[2 * kc + 1], p1l1[2 * kc + 1]};
                    MMA_BF16(acc1[jd], ah, bh[kc]);
                    MMA_BF16(acc1[jd], al_, bh[kc]);
                    MMA_BF16(acc1[jd], ah, bl[kc]);
                }
            }
            if (act2) {
#pragma unroll
                for (int kc = 0; kc < 4; kc++) {
                    unsigned ah[4] = {p2h0[2 * kc], p2h1[2 * kc],
                                      p2h0[2 * kc + 1], p2h1[2 * kc + 1]};
                    unsigned al_[4] = {p2l0[2 * kc], p2l1[2 * kc],
                                       p2l0[2 * kc + 1], p2l1[2 * kc + 1]};
                    MMA_BF16(acc2[jd], ah, bh[kc]);
                    MMA_BF16(acc2[jd], al_, bh[kc]);
                    MMA_BF16(acc2[jd], ah, bl[kc]);
                }
            }
        }
    }

    int row = tid >> 4, col = (tid & 15) << 2;

    // ----- phase 1: merge branch 1 -----
    if (tig == 0) {
        sm_m[warp][g8] = m1a; sm_m[warp][g8 + 8] = m1b;
        sm_l[warp][g8] = l1a; sm_l[warp][g8 + 8] = l1b;
    }
#pragma unroll
    for (int j = 0; j < 8; j++) {
        sacc[warp][g8][8 * j + 2 * tig] = acc1[j][0];
        sacc[warp][g8][8 * j + 2 * tig + 1] = acc1[j][1];
        sacc[warp][g8 + 8][8 * j + 2 * tig] = acc1[j][2];
        sacc[warp][g8 + 8][8 * j + 2 * tig + 1] = acc1[j][3];
    }
    __syncthreads();
    float M1 = sm_m[0][row];
#pragma unroll
    for (int w = 1; w < 8; w++) M1 = fmaxf(M1, sm_m[w][row]);
    float L1 = 0.f;
    float o1[4] = {0, 0, 0, 0};
#pragma unroll
    for (int w = 0; w < 8; w++) {
        float f1 = __expf(sm_m[w][row] - M1);
        L1 += f1 * sm_l[w][row];
        const float* a1 = &sacc[w][row][col];
#pragma unroll
        for (int e = 0; e < 4; e++) o1[e] += f1 * a1[e];
    }
    __syncthreads();

    // ----- phase 2: merge branch 2 -----
    if (tig == 0) {
        sm_m[warp][g8] = m2a; sm_m[warp][g8 + 8] = m2b;
        sm_l[warp][g8] = l2a; sm_l[warp][g8 + 8] = l2b;
    }
#pragma unroll
    for (int j = 0; j < 8; j++) {
        sacc[warp][g8][8 * j + 2 * tig] = acc2[j][0];
        sacc[warp][g8][8 * j + 2 * tig + 1] = acc2[j][1];
        sacc[warp][g8 + 8][8 * j + 2 * tig] = acc2[j][2];
        sacc[warp][g8 + 8][8 * j + 2 * tig + 1] = acc2[j][3];
    }
    __syncthreads();
    float M2 = sm_m[0][row];
#pragma unroll
    for (int w = 1; w < 8; w++) M2 = fmaxf(M2, sm_m[w][row]);
    float L2 = 0.f;
    float o2[4] = {0, 0, 0, 0};
#pragma unroll
    for (int w = 0; w < 8; w++) {
        float f2 = __expf(sm_m[w][row] - M2);
        L2 += f2 * sm_l[w][row];
        const float* a2 = &sacc[w][row][col];
#pragma unroll
        for (int e = 0; e < 4; e++) o2[e] += f2 * a2[e];
    }

    float gg1 = 1.f / (1.f + expf(-g_gate[t * 3 + 1]));
    float gg2 = 1.f / (1.f + expf(-g_gate[t * 3 + 2]));
    float w1 = gg1 / L1, w2 = gg2 / L2;
    size_t oidx = (size_t)t * HID + (g * HG + row) * D + col;
    const float* cur = g_att + oidx;
    float vx = cur[0] + w1 * o1[0] + w2 * o2[0];
    float vy = cur[1] + w1 * o1[1] + w2 * o2[1];
    float vz = cur[2] + w1 * o1[2] + w2 * o2[2];
    float vw = cur[3] + w1 * o1[3] + w2 * o2[3];
    unsigned h0, l0_, h1, l1_;
    split2(vx, vy, h0, l0_);
    split2(vz, vw, h1, l1_);
    unsigned* oph = (unsigned*)(g_ath + oidx);
    unsigned* opl = (unsigned*)(g_atl + oidx);
    oph[0] = h0; oph[1] = h1;
    opl[0] = l0_; opl[1] = l1_;
}

// ------------------------- launch --------------------------------------------
extern "C" void kernel_launch(void* const* d_in, const int* in_sizes, int n_in,
                              void* d_out, int out_size) {
    const float* x   = (const float*)d_in[0];
    const float* Wq  = (const float*)d_in[1];
    const float* Wk  = (const float*)d_in[2];
    const float* Wv  = (const float*)d_in[3];
    const float* Wo  = (const float*)d_in[4];
    const float* Wg  = (const float*)d_in[5];
    const float* Wck = (const float*)d_in[6];
    const float* Wcv = (const float*)d_in[7];
    float* out = (float*)d_out;

    float *pq, *pk;
    cudaGetSymbolAddress((void**)&pq, g_q);
    cudaGetSymbolAddress((void**)&pk, g_k);
    __nv_bfloat16 *xh, *xl, *wqh, *wql, *wkh, *wkl, *wvh, *wvl, *woh, *wol;
    cudaGetSymbolAddress((void**)&xh, g_xh);
    cudaGetSymbolAddress((void**)&xl, g_xl);
    cudaGetSymbolAddress((void**)&wqh, g_wqh);
    cudaGetSymbolAddress((void**)&wql, g_wql);
    cudaGetSymbolAddress((void**)&wkh, g_wkh);
    cudaGetSymbolAddress((void**)&wkl, g_wkl);
    cudaGetSymbolAddress((void**)&wvh, g_wvh);
    cudaGetSymbolAddress((void**)&wvl, g_wvl);
    cudaGetSymbolAddress((void**)&woh, g_woh);
    cudaGetSymbolAddress((void**)&wol, g_wol);

    cudaFuncSetAttribute(gemm_qkv, cudaFuncAttributeMaxDynamicSharedMemorySize,
                         GEMM_SMEM2);
    cudaFuncSetAttribute(gemm_out, cudaFuncAttributeMaxDynamicSharedMemorySize,
                         GEMM_SMEM2);

    const int NELT = T * HID;
    const int NKV = G * D * HID;
    split_kernel<<<NELT / 1024, 256>>>(x, xh, xl, NELT);
    split_kernel<<<NELT / 1024, 256>>>(Wq, wqh, wql, NELT);
    split_kernel<<<NKV / 1024, 256>>>(Wk, wkh, wkl, NKV);
    split_kernel<<<NKV / 1024, 256>>>(Wv, wvh, wvl, NKV);
    split_kernel<<<NELT / 1024, 256>>>(Wo, woh, wol, NELT);
    rope_table_kernel<<<T, 32>>>();

    gemm_qkv<<<dim3(18, T / 128), 256, GEMM_SMEM2>>>();
    gate_kernel<<<T, 96>>>(x, Wg);
    rope_apply_kernel<<<T, 256>>>(pq, HQ);
    rope_apply_kernel<<<T, 64>>>(pk, G);
    kvsplit_kernel<<<(T * G * D) / 256, 256>>>();
    compress_kernel<<<dim3(C_NUM, G, 2), 256>>>(Wck, Wcv);
    comp_attn_kernel<<<dim3(T, G), 256>>>();
    select_kernel<<<dim3(T, G), 32>>>();
    attn_mma_kernel<<<dim3(T, G), 256>>>();

    gemm_out<<<dim3(HID / 128, T / 128), 256, GEMM_SMEM2>>>(out);
}

// round 15
// speedup vs baseline: 1.0939x; 1.0939x over previous
#include <cuda_runtime.h>
#include <cuda_bf16.h>
#include <math.h>
#include <stdint.h>

#define T 2048
#define HID 2048
#define HQ 32
#define G 2
#define D 64
#define HG 16          // HQ / G
#define C_NUM 127      // compressed windows
#define TOPK 16
#define WINDOW 512
#define SCALE 0.125f

// ------------------------- scratch (device globals; no allocs) --------------
__device__ float g_q[T * HQ * D];
__device__ float g_k[T * G * D];
__device__ float g_v[T * G * D];
__device__ float g_gate[T * 3];
__device__ float g_psum[G * T * 128];
__device__ unsigned g_sel[G * T];
__device__ float g_att[T * HQ * D];
__device__ float g_cos[T * 32];
__device__ float g_sin[T * 32];

// bf16 split buffers
__device__ __align__(16) __nv_bfloat16 g_xh[T * HID];
__device__ __align__(16) __nv_bfloat16 g_xl[T * HID];
__device__ __align__(16) __nv_bfloat16 g_wqh[HQ * D * HID];
__device__ __align__(16) __nv_bfloat16 g_wql[HQ * D * HID];
__device__ __align__(16) __nv_bfloat16 g_wkh[G * D * HID];
__device__ __align__(16) __nv_bfloat16 g_wkl[G * D * HID];
__device__ __align__(16) __nv_bfloat16 g_wvh[G * D * HID];
__device__ __align__(16) __nv_bfloat16 g_wvl[G * D * HID];
__device__ __align__(16) __nv_bfloat16 g_woh[HID * HID];
__device__ __align__(16) __nv_bfloat16 g_wol[HID * HID];
__device__ __align__(16) __nv_bfloat16 g_ath[T * HID];
__device__ __align__(16) __nv_bfloat16 g_atl[T * HID];
// attention K/V bf16 hi/lo, FRAGMENT-PERMUTED layouts
__device__ __align__(16) __nv_bfloat16 g_kh[T * G * D];
__device__ __align__(16) __nv_bfloat16 g_kl[T * G * D];
__device__ __align__(16) __nv_bfloat16 g_vth[G * D * T];
__device__ __align__(16) __nv_bfloat16 g_vtl[G * D * T];
// compressed K / V^T, fragment-permuted bf16 hi/lo (zero-init pads)
__device__ __align__(16) __nv_bfloat16 g_ckh[G * 128 * 64];
__device__ __align__(16) __nv_bfloat16 g_ckl[G * 128 * 64];
__device__ __align__(16) __nv_bfloat16 g_cvth[G * 64 * 128];
__device__ __align__(16) __nv_bfloat16 g_cvtl[G * 64 * 128];

// ------------------------- helpers ------------------------------------------
__device__ __forceinline__ void split2(float x, float y, unsigned& h,
                                       unsigned& l) {
    __nv_bfloat162 hh = __floats2bfloat162_rn(x, y);
    float hx = __bfloat162float(__low2bfloat16(hh));
    float hy = __bfloat162float(__high2bfloat16(hh));
    __nv_bfloat162 ll = __floats2bfloat162_rn(x - hx, y - hy);
    h = *reinterpret_cast<unsigned*>(&hh);
    l = *reinterpret_cast<unsigned*>(&ll);
}

__device__ __forceinline__ int frag_perm(int o) {
    return ((o & 3) << 3) + ((o >> 3) << 1) + ((o >> 2) & 1);
}

// ------------------------- fp32 -> bf16 hi/lo split --------------------------
__global__ void split_kernel(const float* __restrict__ src,
                             __nv_bfloat16* __restrict__ hi,
                             __nv_bfloat16* __restrict__ lo, int n) {
    int i = (blockIdx.x * blockDim.x + threadIdx.x) * 4;
    if (i >= n) return;
    float4 v = *(const float4*)(src + i);
    unsigned h0, l0, h1, l1;
    split2(v.x, v.y, h0, l0);
    split2(v.z, v.w, h1, l1);
    ((unsigned*)(hi + i))[0] = h0;
    ((unsigned*)(hi + i))[1] = h1;
    ((unsigned*)(lo + i))[0] = l0;
    ((unsigned*)(lo + i))[1] = l1;
}

// K split (permuted d) + V transpose/split (permuted t within 64-block)
__global__ void kvsplit_kernel() {
    int i = blockIdx.x * blockDim.x + threadIdx.x;  // over T*G*D
    int d = i & 63;
    float kv = g_k[i];
    __nv_bfloat16 h = __float2bfloat16(kv);
    int nd = (frag_perm(d >> 1) << 1) + (d & 1);
    g_kh[(i - d) + nd] = h;
    g_kl[(i - d) + nd] = __float2bfloat16(kv - __bfloat162float(h));

    int t = i >> 7, gd = i & 127;
    float vv = g_v[i];
    __nv_bfloat16 vh = __float2bfloat16(vv);
    int tt = t & 63;
    int nt = (t & ~63) + (frag_perm(tt >> 1) << 1) + (tt & 1);
    int o = gd * T + nt;
    g_vth[o] = vh;
    g_vtl[o] = __float2bfloat16(vv - __bfloat162float(vh));
}

// ------------------------- MMA macros ----------------------------------------
#define SMS 40
#define ARR_BYTES 10240           // 128 rows x 40 bf16 x 2B
#define STAGE_B (4 * ARR_BYTES)   // Ah,Al,Bh,Bl
#define GEMM_SMEM2 (2 * STAGE_B)  // 80 KB

#define LDSM4(r0, r1, r2, r3, addr)                                       \
    asm volatile("ldmatrix.sync.aligned.m8n8.x4.shared.b16 "              \
                 "{%0,%1,%2,%3}, [%4];"                                   \
                 : "=r"(r0), "=r"(r1), "=r"(r2), "=r"(r3) : "r"(addr))

#define MMA_BF16(dd, aa, bb)                                              \
    asm volatile("mma.sync.aligned.m16n8k16.row.col.f32.bf16.bf16.f32 "   \
                 "{%0,%1,%2,%3},{%4,%5,%6,%7},{%8,%9},{%0,%1,%2,%3};"     \
                 : "+f"(dd[0]), "+f"(dd[1]), "+f"(dd[2]), "+f"(dd[3])     \
                 : "r"(aa[0]), "r"(aa[1]), "r"(aa[2]), "r"(aa[3]),        \
                   "r"(bb[0]), "r"(bb[1]))

__device__ __forceinline__ void cp16(unsigned dst, const void* src) {
    asm volatile("cp.async.cg.shared.global [%0], [%1], 16;" ::"r"(dst),
                 "l"(src));
}
#define CP_COMMIT() asm volatile("cp.async.commit_group;")

// cp.async 2-stage double-buffered bf16x3 GEMM core, 2 CTAs/SM
__device__ __forceinline__ void gemm_core(
    const __nv_bfloat16* __restrict__ Ah, const __nv_bfloat16* __restrict__ Al,
    const __nv_bfloat16* __restrict__ Bh, const __nv_bfloat16* __restrict__ Bl,
    float* __restrict__ C, int ldc, int bm, int bnw, int bnc, int K) {
    extern __shared__ __align__(16) char dsm[];

    int tid = threadIdx.x;
    int lrow = tid >> 1, lcol = (tid & 1) << 4;
    int wid = tid >> 5, lane = tid & 31;
    int wm = wid & 1, wn = wid >> 1;
    int m0 = wm * 64, n0 = wn * 32;
    int g8 = lane >> 2, tig = lane & 3;

    const __nv_bfloat16* pAh = Ah + (size_t)(bm + lrow) * K + lcol;
    const __nv_bfloat16* pAl = Al + (size_t)(bm + lrow) * K + lcol;
    const __nv_bfloat16* pBh = Bh + (size_t)(bnw + lrow) * K + lcol;
    const __nv_bfloat16* pBl = Bl + (size_t)(bnw + lrow) * K + lcol;

    float acc[4][4][4];
#pragma unroll
    for (int i = 0; i < 4; i++)
#pragma unroll
        for (int j = 0; j < 4; j++)
#pragma unroll
            for (int r = 0; r < 4; r++) acc[i][j][r] = 0.f;

    int aoff = (m0 + (lane & 7) + ((lane >> 3) & 1) * 8) * SMS + (lane >> 4) * 8;
    int boff = (n0 + (lane & 7) + (lane >> 4) * 8) * SMS + ((lane >> 3) & 1) * 8;
    unsigned sbase = (unsigned)__cvta_generic_to_shared(dsm);
    unsigned sidx = (unsigned)((lrow * SMS + lcol) * 2);

    int niter = K / 32;
#pragma unroll
    for (int s = 0; s < 2; s++) {
        unsigned o = sbase + s * STAGE_B + sidx;
        int k0 = s * 32;
        cp16(o, pAh + k0);
        cp16(o + 16, pAh + k0 + 8);
        cp16(o + ARR_BYTES, pAl + k0);
        cp16(o + ARR_BYTES + 16, pAl + k0 + 8);
        cp16(o + 2 * ARR_BYTES, pBh + k0);
        cp16(o + 2 * ARR_BYTES + 16, pBh + k0 + 8);
        cp16(o + 3 * ARR_BYTES, pBl + k0);
        cp16(o + 3 * ARR_BYTES + 16, pBl + k0 + 8);
        CP_COMMIT();
    }

    for (int it = 0; it < niter; it++) {
        asm volatile("cp.async.wait_group 1;");
        __syncthreads();
        unsigned cb = sbase + (it & 1) * STAGE_B;
        unsigned uAh = cb, uAl = cb + ARR_BYTES;
        unsigned uBh = cb + 2 * ARR_BYTES, uBl = cb + 3 * ARR_BYTES;
#pragma unroll
        for (int kk = 0; kk < 32; kk += 16) {
            unsigned bh[4][2], bl[4][2];
#pragma unroll
            for (int j2 = 0; j2 < 2; j2++) {
                unsigned bd = (unsigned)((boff + j2 * 16 * SMS + kk) * 2);
                LDSM4(bh[2 * j2][0], bh[2 * j2][1], bh[2 * j2 + 1][0],
                      bh[2 * j2 + 1][1], uBh + bd);
                LDSM4(bl[2 * j2][0], bl[2 * j2][1], bl[2 * j2 + 1][0],
                      bl[2 * j2 + 1][1], uBl + bd);
            }
#pragma unroll
            for (int i = 0; i < 4; i++) {
                unsigned ah[4], al[4];
                unsigned ad = (unsigned)((aoff + i * 16 * SMS + kk) * 2);
                LDSM4(ah[0], ah[1], ah[2], ah[3], uAh + ad);
                LDSM4(al[0], al[1], al[2], al[3], uAl + ad);
#pragma unroll
                for (int j = 0; j < 4; j++) {
                    MMA_BF16(acc[i][j], ah, bh[j]);
                    MMA_BF16(acc[i][j], ah, bl[j]);
                    MMA_BF16(acc[i][j], al, bh[j]);
                }
            }
        }
        __syncthreads();
        if (it + 2 < niter) {
            unsigned o = cb + sidx;
            int k0 = (it + 2) * 32;
            cp16(o, pAh + k0);
            cp16(o + 16, pAh + k0 + 8);
            cp16(o + ARR_BYTES, pAl + k0);
            cp16(o + ARR_BYTES + 16, pAl + k0 + 8);
            cp16(o + 2 * ARR_BYTES, pBh + k0);
            cp16(o + 2 * ARR_BYTES + 16, pBh + k0 + 8);
            cp16(o + 3 * ARR_BYTES, pBl + k0);
            cp16(o + 3 * ARR_BYTES + 16, pBl + k0 + 8);
        }
        CP_COMMIT();
    }
#pragma unroll
    for (int i = 0; i < 4; i++) {
        int r0 = bm + m0 + i * 16 + g8;
#pragma unroll
        for (int j = 0; j < 4; j++) {
            int col = bnc + n0 + j * 8 + tig * 2;
            *(float2*)(C + (size_t)r0 * ldc + col) =
                make_float2(acc[i][j][0], acc[i][j][1]);
            *(float2*)(C + (size_t)(r0 + 8) * ldc + col) =
                make_float2(acc[i][j][2], acc[i][j][3]);
        }
    }
}

// ------------------------- QKV fused GEMM ------------------------------------
__global__ __launch_bounds__(256, 2) void gemm_qkv() {
    int bx = blockIdx.x;
    const __nv_bfloat16 *Bh, *Bl;
    float* C;
    int ldc, bnw, bnc;
    if (bx < 16) {
        Bh = g_wqh; Bl = g_wql; C = g_q; ldc = HQ * D;
        bnw = bx * 128; bnc = bx * 128;
    } else if (bx == 16) {
        Bh = g_wkh; Bl = g_wkl; C = g_k; ldc = G * D; bnw = 0; bnc = 0;
    } else {
        Bh = g_wvh; Bl = g_wvl; C = g_v; ldc = G * D; bnw = 0; bnc = 0;
    }
    gemm_core(g_xh, g_xl, Bh, Bl, C, ldc, blockIdx.y * 128, bnw, bnc, HID);
}

// ------------------------- Wo GEMM --------------------------------------------
__global__ __launch_bounds__(256, 2) void gemm_out(float* __restrict__ C) {
    gemm_core(g_ath, g_atl, g_woh, g_wol, C, HID, blockIdx.y * 128,
              blockIdx.x * 128, blockIdx.x * 128, HID);
}

// ------------------------- gate = x @ Wgate^T --------------------------------
__global__ void gate_kernel(const float* __restrict__ x,
                            const float* __restrict__ Wg) {
    int t = blockIdx.x;
    int w = threadIdx.x >> 5, lane = threadIdx.x & 31;
    const float* xr = x + (size_t)t * HID;
    const float* wr = Wg + (size_t)w * HID;
    float acc = 0.f;
    for (int i = lane; i < HID; i += 32) acc += xr[i] * wr[i];
#pragma unroll
    for (int off = 16; off; off >>= 1)
        acc += __shfl_xor_sync(0xffffffffu, acc, off);
    if (!lane) g_gate[t * 3 + w] = acc;
}

// ------------------------- RoPE: table + apply --------------------------------
__global__ void rope_table_kernel() {
    int t = blockIdx.x, d = threadIdx.x;
    double inv = exp(-(double)d * (log(10000.0) / 32.0));
    double sn, cs;
    sincos((double)t * inv, &sn, &cs);
    g_cos[t * 32 + d] = (float)cs;
    g_sin[t * 32 + d] = (float)sn;
}

__global__ void rope_apply_kernel(float* x, int nh) {
    int t = blockIdx.x;
    for (int idx = threadIdx.x; idx < nh * 32; idx += blockDim.x) {
        int hh = idx >> 5, d = idx & 31;
        float cs = g_cos[t * 32 + d], sn = g_sin[t * 32 + d];
        float* p = x + ((size_t)t * nh + hh) * D;
        float x1 = p[d], x2 = p[d + 32];
        p[d]      = x1 * cs - x2 * sn;
        p[d + 32] = x2 * cs + x1 * sn;
    }
}

// ------------------------- compression -> fragment-permuted bf16 -------------
__global__ __launch_bounds__(256) void compress_kernel(
    const float* __restrict__ Wck, const float* __restrict__ Wcv) {
    int c = blockIdx.x, g = blockIdx.y, which = blockIdx.z;
    const float* src = which ? g_v : g_k;
    const float* W = (which ? Wcv : Wck) + (size_t)g * 2048 * D;
    __shared__ float win[32 * 64];
    __shared__ float partial[4][64];
    int tid = threadIdx.x;
    for (int i = tid; i < 2048; i += 256) {
        int j = i >> 6, dd = i & 63;
        win[i] = src[((size_t)(16 * c + j) * G + g) * D + dd];
    }
    __syncthreads();
    int d = tid & 63, q = tid >> 6;
    float acc = 0.f;
    const float* Wp = W + (size_t)(q * 512) * D + d;
    const float* wp = win + q * 512;
#pragma unroll 8
    for (int f = 0; f < 512; f++) acc += wp[f] * Wp[(size_t)f * D];
    partial[q][d] = acc;
    __syncthreads();
    if (tid < 64) {
        float val = partial[0][tid] + partial[1][tid] + partial[2][tid] +
                    partial[3][tid];
        __nv_bfloat16 h = __float2bfloat16(val);
        __nv_bfloat16 lo = __float2bfloat16(val - __bfloat162float(h));
        if (which == 0) {
            int nd = (frag_perm(tid >> 1) << 1) + (tid & 1);
            size_t o = ((size_t)g * 128 + c) * 64 + nd;
            g_ckh[o] = h;
            g_ckl[o] = lo;
        } else {
            int pc = (c & ~63) + (frag_perm((c & 63) >> 1) << 1) + (c & 1);
            size_t o = ((size_t)g * 64 + tid) * 128 + pc;
            g_cvth[o] = h;
            g_cvtl[o] = lo;
        }
    }
}

// ------------------------- compressed attention (MMA) + psum -----------------
__global__ __launch_bounds__(256) void comp_attn_kernel() {
    int t = blockIdx.x, g = blockIdx.y;
    int tid = threadIdx.x;
    int warp = tid >> 5, lane = tid & 31;
    int g8 = lane >> 2, tig = lane & 3;
    int h = tid >> 4, m16 = tid & 15;

    __shared__ float sS[16][128];
    __shared__ float sp[16][128];

    int nc = (t >= 31) ? ((t - 31) >> 4) + 1 : 0;
    float gate0 = 1.f / (1.f + expf(-g_gate[t * 3 + 0]));
    float* psum_out = g_psum + ((size_t)g * T + t) * 128;
    float* out = g_att + ((size_t)t * HQ + g * HG) * D;

    if (nc == 0) {
        int d0 = m16 << 2;
        *(float4*)(out + h * D + d0) = make_float4(0.f, 0.f, 0.f, 0.f);
        if (tid < 128) psum_out[tid] = 0.f;
        return;
    }

    // q fragments hi/lo, pre-scaled by SCALE
    unsigned aqh[4][4], aql[4][4];
    {
        const float* qbase = g_q + ((size_t)t * HQ + g * HG) * D;
#pragma unroll
        for (int c = 0; c < 4; c++) {
            int d0 = c * 16 + 2 * tig;
            float2 v00 = *(const float2*)(qbase + g8 * D + d0);
            float2 v10 = *(const float2*)(qbase + (g8 + 8) * D + d0);
            float2 v01 = *(const float2*)(qbase + g8 * D + d0 + 8);
            float2 v11 = *(const float2*)(qbase + (g8 + 8) * D + d0 + 8);
            split2(v00.x * SCALE, v00.y * SCALE, aqh[c][0], aql[c][0]);
            split2(v10.x * SCALE, v10.y * SCALE, aqh[c][1], aql[c][1]);
            split2(v01.x * SCALE, v01.y * SCALE, aqh[c][2], aql[c][2]);
            split2(v11.x * SCALE, v11.y * SCALE, aqh[c][3], aql[c][3]);
        }
    }

    {
#pragma unroll
        for (int j = 0; j < 2; j++) {
            float S[4] = {0.f, 0.f, 0.f, 0.f};
            int crow = 16 * warp + 8 * j + g8;
            size_t rowoff = ((size_t)g * 128 + crow) * 64;
            const uint4* ph = (const uint4*)(g_ckh + rowoff) + tig * 2;
            const uint4* pl = (const uint4*)(g_ckl + rowoff) + tig * 2;
            uint4 H0 = ph[0], H1 = ph[1];
            uint4 L0 = pl[0], L1 = pl[1];
            unsigned bh[4][2] = {{H0.x, H0.y}, {H0.z, H0.w},
                                 {H1.x, H1.y}, {H1.z, H1.w}};
            unsigned bl[4][2] = {{L0.x, L0.y}, {L0.z, L0.w},
                                 {L1.x, L1.y}, {L1.z, L1.w}};
#pragma unroll
            for (int c4 = 0; c4 < 4; c4++) {
                MMA_BF16(S, aqh[c4], bh[c4]);
                MMA_BF16(S, aql[c4], bh[c4]);
                MMA_BF16(S, aqh[c4], bl[c4]);
            }
            int cc = 16 * warp + 8 * j + 2 * tig;
            sS[g8][cc] = S[0];
            sS[g8][cc + 1] = S[1];
            sS[g8 + 8][cc] = S[2];
            sS[g8 + 8][cc + 1] = S[3];
        }
    }
    __syncthreads();

    {
        float sv[8];
        float mx = -INFINITY;
#pragma unroll
        for (int r = 0; r < 8; r++) {
            int c = r * 16 + m16;
            float v = (c < nc) ? sS[h][c] : -INFINITY;
            sv[r] = v;
            mx = fmaxf(mx, v);
        }
#pragma unroll
        for (int off = 8; off; off >>= 1)
            mx = fmaxf(mx, __shfl_xor_sync(0xffffffffu, mx, off, 16));
        float l = 0.f;
#pragma unroll
        for (int r = 0; r < 8; r++) {
            sv[r] = __expf(sv[r] - mx);
            l += sv[r];
        }
#pragma unroll
        for (int off = 8; off; off >>= 1)
            l += __shfl_xor_sync(0xffffffffu, l, off, 16);
        float invl = 1.f / l;
#pragma unroll
        for (int r = 0; r < 8; r++) sp[h][r * 16 + m16] = sv[r] * invl;
    }
    __syncthreads();

    if (tid < 128) {
        float s = 0.f;
        if (tid < nc) {
#pragma unroll
            for (int hh = 0; hh < HG; hh++) s += sp[hh][tid];
        }
        psum_out[tid] = s;
    }

    float acc[4] = {0.f, 0.f, 0.f, 0.f};
#pragma unroll
    for (int b64 = 0; b64 < 2; b64++) {
        size_t rowoff = ((size_t)g * 64 + 8 * warp + g8) * 128 + 64 * b64;
        const uint4* pvh = (const uint4*)(g_cvth + rowoff) + tig * 2;
        const uint4* pvl = (const uint4*)(g_cvtl + rowoff) + tig * 2;
        uint4 H0 = pvh[0], H1 = pvh[1];
        uint4 L0 = pvl[0], L1 = pvl[1];
        unsigned bh[4][2] = {{H0.x, H0.y}, {H0.z, H0.w},
                             {H1.x, H1.y}, {H1.z, H1.w}};
        unsigned bl[4][2] = {{L0.x, L0.y}, {L0.z, L0.w},
                             {L1.x, L1.y}, {L1.z, L1.w}};
#pragma unroll
        for (int kcl = 0; kcl < 4; kcl++) {
            int kc = 4 * b64 + kcl;
            float2 p00 = *(const float2*)&sp[g8][16 * kc + 2 * tig];
            float2 p10 = *(const float2*)&sp[g8 + 8][16 * kc + 2 * tig];
            float2 p01 = *(const float2*)&sp[g8][16 * kc + 8 + 2 * tig];
            float2 p11 = *(const float2*)&sp[g8 + 8][16 * kc + 8 + 2 * tig];
            unsigned ah[4], al[4];
            split2(p00.x, p00.y, ah[0], al[0]);
            split2(p10.x, p10.y, ah[1], al[1]);
            split2(p01.x, p01.y, ah[2], al[2]);
            split2(p11.x, p11.y, ah[3], al[3]);
            MMA_BF16(acc, ah, bh[kcl]);
            MMA_BF16(acc, al, bh[kcl]);
            MMA_BF16(acc, ah, bl[kcl]);
        }
    }
    int dcol = 8 * warp + 2 * tig;
    out[g8 * D + dcol] = gate0 * acc[0];
    out[g8 * D + dcol + 1] = gate0 * acc[1];
    out[(g8 + 8) * D + dcol] = gate0 * acc[2];
    out[(g8 + 8) * D + dcol + 1] = gate0 * acc[3];
}

// ------------------------- block score + stable top-k ------------------------
__global__ void select_kernel() {
    int t = blockIdx.x, g = blockIdx.y;
    int b = threadIdx.x;
    const float* ps = g_psum + ((size_t)g * T + t) * 128;
    float sc = 0.f;
    int clo = 4 * b - 1; if (clo < 0) clo = 0;
    int chi = 4 * b + 3; if (chi > C_NUM - 1) chi = C_NUM - 1;
    for (int c = clo; c <= chi; c++) sc += ps[c];
    int qb = t >> 6;
    bool causal = (b <= qb);
    bool forced = (b < 1) || ((qb - b < 2) && causal);
    float val = causal ? (forced ? INFINITY : sc) : -INFINITY;
    unsigned selbits = 0;
    for (int it = 0; it < TOPK; it++) {
        float rv = val; int ri = b;
#pragma unroll
        for (int off = 16; off; off >>= 1) {
            float ov = __shfl_xor_sync(0xffffffffu, rv, off);
            int oi = __shfl_xor_sync(0xffffffffu, ri, off);
            if (ov > rv || (ov == rv && oi < ri)) { rv = ov; ri = oi; }
        }
        if (rv == -INFINITY) break;
        selbits |= (1u << ri);
        if (b == ri) val = -INFINITY;
    }
    if (b == 0) g_sel[(size_t)g * T + t] = selbits;
}

// ------------------------- merged MMA flash attention ------------------------
// Union-block schedule; QK once per block; separate PV per branch (register
// budget: only one branch's P fragments live at a time).
__global__ __launch_bounds__(256) void attn_mma_kernel() {
    int t = blockIdx.x, g = blockIdx.y;
    int tid = threadIdx.x;
    int warp = tid >> 5, lane = tid & 31;
    int g8 = lane >> 2, tig = lane & 3;

    __shared__ float sm_m[8][16];
    __shared__ float sm_l[8][16];
    __shared__ float sacc[8][16][64];

    int qb = t >> 6;
    int lo = t - WINDOW; if (lo < 0) lo = 0;
    unsigned msel = g_sel[(size_t)g * T + t];
    unsigned mwin = ((2u << qb) - 1) & ~((1u << (lo >> 6)) - 1);
    unsigned mall = msel | mwin;

    // q fragments hi/lo, pre-scaled by SCALE
    unsigned aqh[4][4], aql[4][4];
    {
        const float* qbase = g_q + ((size_t)t * HQ + g * HG) * D;
#pragma unroll
        for (int c = 0; c < 4; c++) {
            int d0 = c * 16 + 2 * tig;
            float2 v00 = *(const float2*)(qbase + g8 * D + d0);
            float2 v10 = *(const float2*)(qbase + (g8 + 8) * D + d0);
            float2 v01 = *(const float2*)(qbase + g8 * D + d0 + 8);
            float2 v11 = *(const float2*)(qbase + (g8 + 8) * D + d0 + 8);
            split2(v00.x * SCALE, v00.y * SCALE, aqh[c][0], aql[c][0]);
            split2(v10.x * SCALE, v10.y * SCALE, aqh[c][1], aql[c][1]);
            split2(v01.x * SCALE, v01.y * SCALE, aqh[c][2], aql[c][2]);
            split2(v11.x * SCALE, v11.y * SCALE, aqh[c][3], aql[c][3]);
        }
    }

    float m1a = -INFINITY, m1b = -INFINITY, l1a = 0.f, l1b = 0.f;
    float m2a = -INFINITY, m2b = -INFINITY, l2a = 0.f, l2b = 0.f;
    float acc1[8][4], acc2[8][4];
#pragma unroll
    for (int j = 0; j < 8; j++)
#pragma unroll
        for (int r = 0; r < 4; r++) { acc1[j][r] = 0.f; acc2[j][r] = 0.f; }

    unsigned rem = mall;
    int bidx = 0;
    while (rem) {
        int b = __ffs(rem) - 1;
        rem &= rem - 1;
        if ((bidx++ & 7) != warp) continue;
        int sbase = b << 6;
        int smax = t - sbase; if (smax > 63) smax = 63;
        bool act1 = (msel >> b) & 1u;
        bool act2 = (mwin >> b) & 1u;
        int smin2 = lo - sbase; if (smin2 < 0) smin2 = 0;

        // ----- QK once (q pre-scaled) -----
        float S[8][4];
#pragma unroll
        for (int j = 0; j < 8; j++)
#pragma unroll
            for (int r = 0; r < 4; r++) S[j][r] = 0.f;
#pragma unroll
        for (int j = 0; j < 8; j++) {
            size_t rowoff = ((size_t)(sbase + 8 * j + g8) * G + g) * D;
            const uint4* ph = (const uint4*)(g_kh + rowoff) + tig * 2;
            const uint4* pl = (const uint4*)(g_kl + rowoff) + tig * 2;
            uint4 H0 = ph[0], H1 = ph[1];
            uint4 L0 = pl[0], L1 = pl[1];
            unsigned bh[4][2] = {{H0.x, H0.y}, {H0.z, H0.w},
                                 {H1.x, H1.y}, {H1.z, H1.w}};
            unsigned bl[4][2] = {{L0.x, L0.y}, {L0.z, L0.w},
                                 {L1.x, L1.y}, {L1.z, L1.w}};
#pragma unroll
            for (int c = 0; c < 4; c++) {
                MMA_BF16(S[j], aqh[c], bh[c]);
                MMA_BF16(S[j], aql[c], bh[c]);
                MMA_BF16(S[j], aqh[c], bl[c]);
            }
        }

        int soff = 2 * tig;

        // ----- branch 1: sparse (smin = 0) -----
        if (act1) {
            float bmax0 = -INFINITY, bmax1 = -INFINITY;
#pragma unroll
            for (int j = 0; j < 8; j++) {
                int s0i = 8 * j + soff, s1i = s0i + 1;
                if (s0i <= smax) {
                    bmax0 = fmaxf(bmax0, S[j][0]);
                    bmax1 = fmaxf(bmax1, S[j][2]);
                }
                if (s1i <= smax) {
                    bmax0 = fmaxf(bmax0, S[j][1]);
                    bmax1 = fmaxf(bmax1, S[j][3]);
                }
            }
            bmax0 = fmaxf(bmax0, __shfl_xor_sync(0xffffffffu, bmax0, 1));
            bmax0 = fmaxf(bmax0, __shfl_xor_sync(0xffffffffu, bmax0, 2));
            bmax1 = fmaxf(bmax1, __shfl_xor_sync(0xffffffffu, bmax1, 1));
            bmax1 = fmaxf(bmax1, __shfl_xor_sync(0xffffffffu, bmax1, 2));
            float mn0 = fmaxf(m1a, bmax0), mn1 = fmaxf(m1b, bmax1);
            float cor0 = __expf(m1a - mn0), cor1 = __expf(m1b - mn1);
            m1a = mn0; m1b = mn1;

            unsigned ph0[8], ph1[8], pl0[8], pl1[8];
            float ps0 = 0.f, ps1 = 0.f;
#pragma unroll
            for (int j = 0; j < 8; j++) {
                int s0i = 8 * j + soff, s1i = s0i + 1;
                float p0 = (s0i <= smax) ? __expf(S[j][0] - mn0) : 0.f;
                float p1 = (s1i <= smax) ? __expf(S[j][1] - mn0) : 0.f;
                float p2 = (s0i <= smax) ? __expf(S[j][2] - mn1) : 0.f;
                float p3 = (s1i <= smax) ? __expf(S[j][3] - mn1) : 0.f;
                ps0 += p0 + p1;
                ps1 += p2 + p3;
                split2(p0, p1, ph0[j], pl0[j]);
                split2(p2, p3, ph1[j], pl1[j]);
            }
            ps0 += __shfl_xor_sync(0xffffffffu, ps0, 1);
            ps0 += __shfl_xor_sync(0xffffffffu, ps0, 2);
            ps1 += __shfl_xor_sync(0xffffffffu, ps1, 1);
            ps1 += __shfl_xor_sync(0xffffffffu, ps1, 2);
            l1a = l1a * cor0 + ps0;
            l1b = l1b * cor1 + ps1;
#pragma unroll
            for (int j = 0; j < 8; j++) {
                acc1[j][0] *= cor0; acc1[j][1] *= cor0;
                acc1[j][2] *= cor1; acc1[j][3] *= cor1;
            }
#pragma unroll
            for (int jd = 0; jd < 8; jd++) {
                size_t rowoff = ((size_t)(g * D + g8 + 8 * jd)) * T + sbase;
                const uint4* pvh = (const uint4*)(g_vth + rowoff) + tig * 2;
                const uint4* pvl = (const uint4*)(g_vtl + rowoff) + tig * 2;
                uint4 H0 = pvh[0], H1 = pvh[1];
                uint4 L0 = pvl[0], L1 = pvl[1];
                unsigned bh[4][2] = {{H0.x, H0.y}, {H0.z, H0.w},
                                     {H1.x, H1.y}, {H1.z, H1.w}};
                unsigned bl[4][2] = {{L0.x, L0.y}, {L0.z, L0.w},
                                     {L1.x, L1.y}, {L1.z, L1.w}};
#pragma unroll
                for (int kc = 0; kc < 4; kc++) {
                    unsigned ah[4] = {ph0[2 * kc], ph1[2 * kc],
                                      ph0[2 * kc + 1], ph1[2 * kc + 1]};
                    unsigned al_[4] = {pl0[2 * kc], pl1[2 * kc],
                                       pl0[2 * kc + 1], pl1[2 * kc + 1]};
                    MMA_BF16(acc1[jd], ah, bh[kc]);
                    MMA_BF16(acc1[jd], al_, bh[kc]);
                    MMA_BF16(acc1[jd], ah, bl[kc]);
                }
            }
        }

        // ----- branch 2: sliding window [smin2, smax] -----
        if (act2) {
            float bmax0 = -INFINITY, bmax1 = -INFINITY;
#pragma unroll
            for (int j = 0; j < 8; j++) {
                int s0i = 8 * j + soff, s1i = s0i + 1;
                if (s0i >= smin2 && s0i <= smax) {
                    bmax0 = fmaxf(bmax0, S[j][0]);
                    bmax1 = fmaxf(bmax1, S[j][2]);
                }
                if (s1i >= smin2 && s1i <= smax) {
                    bmax0 = fmaxf(bmax0, S[j][1]);
                    bmax1 = fmaxf(bmax1, S[j][3]);
                }
            }
            bmax0 = fmaxf(bmax0, __shfl_xor_sync(0xffffffffu, bmax0, 1));
            bmax0 = fmaxf(bmax0, __shfl_xor_sync(0xffffffffu, bmax0, 2));
            bmax1 = fmaxf(bmax1, __shfl_xor_sync(0xffffffffu, bmax1, 1));
            bmax1 = fmaxf(bmax1, __shfl_xor_sync(0xffffffffu, bmax1, 2));
            float mn0 = fmaxf(m2a, bmax0), mn1 = fmaxf(m2b, bmax1);
            float cor0 = __expf(m2a - mn0), cor1 = __expf(m2b - mn1);
            m2a = mn0; m2b = mn1;

            unsigned ph0[8], ph1[8], pl0[8], pl1[8];
            float ps0 = 0.f, ps1 = 0.f;
#pragma unroll
            for (int j = 0; j < 8; j++) {
                int s0i = 8 * j + soff, s1i = s0i + 1;
                bool v0 = (s0i >= smin2) && (s0i <= smax);
                bool v1 = (s1i >= smin2) && (s1i <= smax);
                float p0 = v0 ? __expf(S[j][0] - mn0) : 0.f;
                float p1 = v1 ? __expf(S[j][1] - mn0) : 0.f;
                float p2 = v0 ? __expf(S[j][2] - mn1) : 0.f;
                float p3 = v1 ? __expf(S[j][3] - mn1) : 0.f;
                ps0 += p0 + p1;
                ps1 += p2 + p3;
                split2(p0, p1, ph0[j], pl0[j]);
                split2(p2, p3, ph1[j], pl1[j]);
            }
            ps0 += __shfl_xor_sync(0xffffffffu, ps0, 1);
            ps0 += __shfl_xor_sync(0xffffffffu, ps0, 2);
            ps1 += __shfl_xor_sync(0xffffffffu, ps1, 1);
            ps1 += __shfl_xor_sync(0xffffffffu, ps1, 2);
            l2a = l2a * cor0 + ps0;
            l2b = l2b * cor1 + ps1;
#pragma unroll
            for (int j = 0; j < 8; j++) {
                acc2[j][0] *= cor0; acc2[j][1] *= cor0;
                acc2[j][2] *= cor1; acc2[j][3] *= cor1;
            }
#pragma unroll
            for (int jd = 0; jd < 8; jd++) {
                size_t rowoff = ((size_t)(g * D + g8 + 8 * jd)) * T + sbase;
                const uint4* pvh = (const uint4*)(g_vth + rowoff) + tig * 2;
                const uint4* pvl = (const uint4*)(g_vtl + rowoff) + tig * 2;
                uint4 H0 = pvh[0], H1 = pvh[1];
                uint4 L0 = pvl[0], L1 = pvl[1];
                unsigned bh[4][2] = {{H0.x, H0.y}, {H0.z, H0.w},
                                     {H1.x, H1.y}, {H1.z, H1.w}};
                unsigned bl[4][2] = {{L0.x, L0.y}, {L0.z, L0.w},
                                     {L1.x, L1.y}, {L1.z, L1.w}};
#pragma unroll
                for (int kc = 0; kc < 4; kc++) {
                    unsigned ah[4] = {ph0[2 * kc], ph1[2 * kc],
                                      ph0[2 * kc + 1], ph1[2 * kc + 1]};
                    unsigned al_[4] = {pl0[2 * kc], pl1[2 * kc],
                                       pl0[2 * kc + 1], pl1[2 * kc + 1]};
                    MMA_BF16(acc2[jd], ah, bh[kc]);
                    MMA_BF16(acc2[jd], al_, bh[kc]);
                    MMA_BF16(acc2[jd], ah, bl[kc]);
                }
            }
        }
    }

    int row = tid >> 4, col = (tid & 15) << 2;

    // ----- phase 1: merge branch 1 -----
    if (tig == 0) {
        sm_m[warp][g8] = m1a; sm_m[warp][g8 + 8] = m1b;
        sm_l[warp][g8] = l1a; sm_l[warp][g8 + 8] = l1b;
    }
#pragma unroll
    for (int j = 0; j < 8; j++) {
        sacc[warp][g8][8 * j + 2 * tig] = acc1[j][0];
        sacc[warp][g8][8 * j + 2 * tig + 1] = acc1[j][1];
        sacc[warp][g8 + 8][8 * j + 2 * tig] = acc1[j][2];
        sacc[warp][g8 + 8][8 * j + 2 * tig + 1] = acc1[j][3];
    }
    __syncthreads();
    float M1 = sm_m[0][row];
#pragma unroll
    for (int w = 1; w < 8; w++) M1 = fmaxf(M1, sm_m[w][row]);
    float L1 = 0.f;
    float o1[4] = {0, 0, 0, 0};
#pragma unroll
    for (int w = 0; w < 8; w++) {
        float f1 = __expf(sm_m[w][row] - M1);
        L1 += f1 * sm_l[w][row];
        const float* a1 = &sacc[w][row][col];
#pragma unroll
        for (int e = 0; e < 4; e++) o1[e] += f1 * a1[e];
    }
    __syncthreads();

    // ----- phase 2: merge branch 2 -----
    if (tig == 0) {
        sm_m[warp][g8] = m2a; sm_m[warp][g8 + 8] = m2b;
        sm_l[warp][g8] = l2a; sm_l[warp][g8 + 8] = l2b;
    }
#pragma unroll
    for (int j = 0; j < 8; j++) {
        sacc[warp][g8][8 * j + 2 * tig] = acc2[j][0];
        sacc[warp][g8][8 * j + 2 * tig + 1] = acc2[j][1];
        sacc[warp][g8 + 8][8 * j + 2 * tig] = acc2[j][2];
        sacc[warp][g8 + 8][8 * j + 2 * tig + 1] = acc2[j][3];
    }
    __syncthreads();
    float M2 = sm_m[0][row];
#pragma unroll
    for (int w = 1; w < 8; w++) M2 = fmaxf(M2, sm_m[w][row]);
    float L2 = 0.f;
    float o2[4] = {0, 0, 0, 0};
#pragma unroll
    for (int w = 0; w < 8; w++) {
        float f2 = __expf(sm_m[w][row] - M2);
        L2 += f2 * sm_l[w][row];
        const float* a2 = &sacc[w][row][col];
#pragma unroll
        for (int e = 0; e < 4; e++) o2[e] += f2 * a2[e];
    }

    float gg1 = 1.f / (1.f + expf(-g_gate[t * 3 + 1]));
    float gg2 = 1.f / (1.f + expf(-g_gate[t * 3 + 2]));
    float w1 = gg1 / L1, w2 = gg2 / L2;
    size_t oidx = (size_t)t * HID + (g * HG + row) * D + col;
    const float* cur = g_att + oidx;
    float vx = cur[0] + w1 * o1[0] + w2 * o2[0];
    float vy = cur[1] + w1 * o1[1] + w2 * o2[1];
    float vz = cur[2] + w1 * o1[2] + w2 * o2[2];
    float vw = cur[3] + w1 * o1[3] + w2 * o2[3];
    unsigned h0, l0_, h1, l1_;
    split2(vx, vy, h0, l0_);
    split2(vz, vw, h1, l1_);
    unsigned* oph = (unsigned*)(g_ath + oidx);
    unsigned* opl = (unsigned*)(g_atl + oidx);
    oph[0] = h0; oph[1] = h1;
    opl[0] = l0_; opl[1] = l1_;
}

// ------------------------- launch --------------------------------------------
extern "C" void kernel_launch(void* const* d_in, const int* in_sizes, int n_in,
                              void* d_out, int out_size) {
    const float* x   = (const float*)d_in[0];
    const float* Wq  = (const float*)d_in[1];
    const float* Wk  = (const float*)d_in[2];
    const float* Wv  = (const float*)d_in[3];
    const float* Wo  = (const float*)d_in[4];
    const float* Wg  = (const float*)d_in[5];
    const float* Wck = (const float*)d_in[6];
    const float* Wcv = (const float*)d_in[7];
    float* out = (float*)d_out;

    float *pq, *pk;
    cudaGetSymbolAddress((void**)&pq, g_q);
    cudaGetSymbolAddress((void**)&pk, g_k);
    __nv_bfloat16 *xh, *xl, *wqh, *wql, *wkh, *wkl, *wvh, *wvl, *woh, *wol;
    cudaGetSymbolAddress((void**)&xh, g_xh);
    cudaGetSymbolAddress((void**)&xl, g_xl);
    cudaGetSymbolAddress((void**)&wqh, g_wqh);
    cudaGetSymbolAddress((void**)&wql, g_wql);
    cudaGetSymbolAddress((void**)&wkh, g_wkh);
    cudaGetSymbolAddress((void**)&wkl, g_wkl);
    cudaGetSymbolAddress((void**)&wvh, g_wvh);
    cudaGetSymbolAddress((void**)&wvl, g_wvl);
    cudaGetSymbolAddress((void**)&woh, g_woh);
    cudaGetSymbolAddress((void**)&wol, g_wol);

    cudaFuncSetAttribute(gemm_qkv, cudaFuncAttributeMaxDynamicSharedMemorySize,
                         GEMM_SMEM2);
    cudaFuncSetAttribute(gemm_out, cudaFuncAttributeMaxDynamicSharedMemorySize,
                         GEMM_SMEM2);

    const int NELT = T * HID;
    const int NKV = G * D * HID;
    split_kernel<<<NELT / 1024, 256>>>(x, xh, xl, NELT);
    split_kernel<<<NELT / 1024, 256>>>(Wq, wqh, wql, NELT);
    split_kernel<<<NKV / 1024, 256>>>(Wk, wkh, wkl, NKV);
    split_kernel<<<NKV / 1024, 256>>>(Wv, wvh, wvl, NKV);
    split_kernel<<<NELT / 1024, 256>>>(Wo, woh, wol, NELT);
    rope_table_kernel<<<T, 32>>>();

    gemm_qkv<<<dim3(18, T / 128), 256, GEMM_SMEM2>>>();
    gate_kernel<<<T, 96>>>(x, Wg);
    rope_apply_kernel<<<T, 256>>>(pq, HQ);
    rope_apply_kernel<<<T, 64>>>(pk, G);
    kvsplit_kernel<<<(T * G * D) / 256, 256>>>();
    compress_kernel<<<dim3(C_NUM, G, 2), 256>>>(Wck, Wcv);
    comp_attn_kernel<<<dim3(T, G), 256>>>();
    select_kernel<<<dim3(T, G), 32>>>();
    attn_mma_kernel<<<dim3(T, G), 256>>>();

    gemm_out<<<dim3(HID / 128, T / 128), 256, GEMM_SMEM2>>>(out);
}

// round 16
// speedup vs baseline: 1.1020x; 1.0074x over previous
#include <cuda_runtime.h>
#include <cuda_bf16.h>
#include <math.h>
#include <stdint.h>

#define T 2048
#define HID 2048
#define HQ 32
#define G 2
#define D 64
#define HG 16          // HQ / G
#define C_NUM 127      // compressed windows
#define TOPK 16
#define WINDOW 512
#define SCALE 0.125f

// ------------------------- scratch (device globals; no allocs) --------------
__device__ float g_q[T * HQ * D];
__device__ float g_k[T * G * D];
__device__ float g_v[T * G * D];
__device__ float g_gate[T * 3];
__device__ unsigned g_sel[G * T];
__device__ float g_att[T * HQ * D];
__device__ float g_cos[T * 32];
__device__ float g_sin[T * 32];

// bf16 split buffers
__device__ __align__(16) __nv_bfloat16 g_xh[T * HID];
__device__ __align__(16) __nv_bfloat16 g_xl[T * HID];
__device__ __align__(16) __nv_bfloat16 g_wqh[HQ * D * HID];
__device__ __align__(16) __nv_bfloat16 g_wql[HQ * D * HID];
__device__ __align__(16) __nv_bfloat16 g_wkh[G * D * HID];
__device__ __align__(16) __nv_bfloat16 g_wkl[G * D * HID];
__device__ __align__(16) __nv_bfloat16 g_wvh[G * D * HID];
__device__ __align__(16) __nv_bfloat16 g_wvl[G * D * HID];
__device__ __align__(16) __nv_bfloat16 g_woh[HID * HID];
__device__ __align__(16) __nv_bfloat16 g_wol[HID * HID];
__device__ __align__(16) __nv_bfloat16 g_ath[T * HID];
__device__ __align__(16) __nv_bfloat16 g_atl[T * HID];
// attention K/V bf16 hi/lo, FRAGMENT-PERMUTED layouts
__device__ __align__(16) __nv_bfloat16 g_kh[T * G * D];
__device__ __align__(16) __nv_bfloat16 g_kl[T * G * D];
__device__ __align__(16) __nv_bfloat16 g_vth[G * D * T];
__device__ __align__(16) __nv_bfloat16 g_vtl[G * D * T];
// compressed K / V^T, fragment-permuted bf16 hi/lo (zero-init pads)
__device__ __align__(16) __nv_bfloat16 g_ckh[G * 128 * 64];
__device__ __align__(16) __nv_bfloat16 g_ckl[G * 128 * 64];
__device__ __align__(16) __nv_bfloat16 g_cvth[G * 64 * 128];
__device__ __align__(16) __nv_bfloat16 g_cvtl[G * 64 * 128];

// ------------------------- helpers ------------------------------------------
__device__ __forceinline__ void split2(float x, float y, unsigned& h,
                                       unsigned& l) {
    __nv_bfloat162 hh = __floats2bfloat162_rn(x, y);
    float hx = __bfloat162float(__low2bfloat16(hh));
    float hy = __bfloat162float(__high2bfloat16(hh));
    __nv_bfloat162 ll = __floats2bfloat162_rn(x - hx, y - hy);
    h = *reinterpret_cast<unsigned*>(&hh);
    l = *reinterpret_cast<unsigned*>(&ll);
}

__device__ __forceinline__ int frag_perm(int o) {
    return ((o & 3) << 3) + ((o >> 3) << 1) + ((o >> 2) & 1);
}

// ------------------------- fused fp32 -> bf16 hi/lo split (5 tensors) --------
// segments (in 1024-elem blocks): x 4096 | Wq 4096 | Wk 256 | Wv 256 | Wo 4096
#define SPLIT_BLOCKS 12800
__global__ void split_all_kernel(const float* __restrict__ x,
                                 const float* __restrict__ Wq,
                                 const float* __restrict__ Wk,
                                 const float* __restrict__ Wv,
                                 const float* __restrict__ Wo) {
    int bid = blockIdx.x;
    const float* src;
    __nv_bfloat16 *hi, *lo;
    int base;
    if (bid < 4096) { src = x; hi = g_xh; lo = g_xl; base = bid; }
    else if (bid < 8192) { src = Wq; hi = g_wqh; lo = g_wql; base = bid - 4096; }
    else if (bid < 8448) { src = Wk; hi = g_wkh; lo = g_wkl; base = bid - 8192; }
    else if (bid < 8704) { src = Wv; hi = g_wvh; lo = g_wvl; base = bid - 8448; }
    else { src = Wo; hi = g_woh; lo = g_wol; base = bid - 8704; }
    int i = (base * 256 + threadIdx.x) * 4;
    float4 v = *(const float4*)(src + i);
    unsigned h0, l0, h1, l1;
    split2(v.x, v.y, h0, l0);
    split2(v.z, v.w, h1, l1);
    ((unsigned*)(hi + i))[0] = h0;
    ((unsigned*)(hi + i))[1] = h1;
    ((unsigned*)(lo + i))[0] = l0;
    ((unsigned*)(lo + i))[1] = l1;
}

// ------------------------- fused K rope + KV split/transpose ------------------
// one thread per rope pair: idx over T * G * 32
__global__ void ropek_kvsplit_kernel() {
    int idx = blockIdx.x * blockDim.x + threadIdx.x;
    int t = idx >> 6;
    int r = idx & 63;
    int g = r >> 5, d = r & 31;
    size_t base = ((size_t)t * G + g) * D;

    float cs = g_cos[t * 32 + d], sn = g_sin[t * 32 + d];
    float k1 = g_k[base + d], k2 = g_k[base + d + 32];
    float kr1 = k1 * cs - k2 * sn;
    float kr2 = k2 * cs + k1 * sn;
    g_k[base + d] = kr1;          // compress_kernel reads roped k
    g_k[base + d + 32] = kr2;

    int tt = t & 63;
    int nt = (t & ~63) + (frag_perm(tt >> 1) << 1) + (tt & 1);
#pragma unroll
    for (int e = 0; e < 2; e++) {
        int dd = d + 32 * e;
        float kv = e ? kr2 : kr1;
        __nv_bfloat16 h = __float2bfloat16(kv);
        int nd = (frag_perm(dd >> 1) << 1) + (dd & 1);
        g_kh[base + nd] = h;
        g_kl[base + nd] = __float2bfloat16(kv - __bfloat162float(h));

        float vv = g_v[base + dd];
        __nv_bfloat16 vh = __float2bfloat16(vv);
        size_t o = (size_t)(g * D + dd) * T + nt;
        g_vth[o] = vh;
        g_vtl[o] = __float2bfloat16(vv - __bfloat162float(vh));
    }
}

// ------------------------- MMA macros ----------------------------------------
#define SMS 40
#define ARR_BYTES 10240           // 128 rows x 40 bf16 x 2B
#define STAGE_B (4 * ARR_BYTES)   // Ah,Al,Bh,Bl
#define GEMM_SMEM2 (2 * STAGE_B)  // 80 KB

#define LDSM4(r0, r1, r2, r3, addr)                                       \
    asm volatile("ldmatrix.sync.aligned.m8n8.x4.shared.b16 "              \
                 "{%0,%1,%2,%3}, [%4];"                                   \
                 : "=r"(r0), "=r"(r1), "=r"(r2), "=r"(r3) : "r"(addr))

#define MMA_BF16(dd, aa, bb)                                              \
    asm volatile("mma.sync.aligned.m16n8k16.row.col.f32.bf16.bf16.f32 "   \
                 "{%0,%1,%2,%3},{%4,%5,%6,%7},{%8,%9},{%0,%1,%2,%3};"     \
                 : "+f"(dd[0]), "+f"(dd[1]), "+f"(dd[2]), "+f"(dd[3])     \
                 : "r"(aa[0]), "r"(aa[1]), "r"(aa[2]), "r"(aa[3]),        \
                   "r"(bb[0]), "r"(bb[1]))

__device__ __forceinline__ void cp16(unsigned dst, const void* src) {
    asm volatile("cp.async.cg.shared.global [%0], [%1], 16;" ::"r"(dst),
                 "l"(src));
}
#define CP_COMMIT() asm volatile("cp.async.commit_group;")

// cp.async 2-stage double-buffered bf16x3 GEMM core, 2 CTAs/SM
__device__ __forceinline__ void gemm_core(
    const __nv_bfloat16* __restrict__ Ah, const __nv_bfloat16* __restrict__ Al,
    const __nv_bfloat16* __restrict__ Bh, const __nv_bfloat16* __restrict__ Bl,
    float* __restrict__ C, int ldc, int bm, int bnw, int bnc, int K) {
    extern __shared__ __align__(16) char dsm[];

    int tid = threadIdx.x;
    int lrow = tid >> 1, lcol = (tid & 1) << 4;
    int wid = tid >> 5, lane = tid & 31;
    int wm = wid & 1, wn = wid >> 1;
    int m0 = wm * 64, n0 = wn * 32;
    int g8 = lane >> 2, tig = lane & 3;

    const __nv_bfloat16* pAh = Ah + (size_t)(bm + lrow) * K + lcol;
    const __nv_bfloat16* pAl = Al + (size_t)(bm + lrow) * K + lcol;
    const __nv_bfloat16* pBh = Bh + (size_t)(bnw + lrow) * K + lcol;
    const __nv_bfloat16* pBl = Bl + (size_t)(bnw + lrow) * K + lcol;

    float acc[4][4][4];
#pragma unroll
    for (int i = 0; i < 4; i++)
#pragma unroll
        for (int j = 0; j < 4; j++)
#pragma unroll
            for (int r = 0; r < 4; r++) acc[i][j][r] = 0.f;

    int aoff = (m0 + (lane & 7) + ((lane >> 3) & 1) * 8) * SMS + (lane >> 4) * 8;
    int boff = (n0 + (lane & 7) + (lane >> 4) * 8) * SMS + ((lane >> 3) & 1) * 8;
    unsigned sbase = (unsigned)__cvta_generic_to_shared(dsm);
    unsigned sidx = (unsigned)((lrow * SMS + lcol) * 2);

    int niter = K / 32;
#pragma unroll
    for (int s = 0; s < 2; s++) {
        unsigned o = sbase + s * STAGE_B + sidx;
        int k0 = s * 32;
        cp16(o, pAh + k0);
        cp16(o + 16, pAh + k0 + 8);
        cp16(o + ARR_BYTES, pAl + k0);
        cp16(o + ARR_BYTES + 16, pAl + k0 + 8);
        cp16(o + 2 * ARR_BYTES, pBh + k0);
        cp16(o + 2 * ARR_BYTES + 16, pBh + k0 + 8);
        cp16(o + 3 * ARR_BYTES, pBl + k0);
        cp16(o + 3 * ARR_BYTES + 16, pBl + k0 + 8);
        CP_COMMIT();
    }

    for (int it = 0; it < niter; it++) {
        asm volatile("cp.async.wait_group 1;");
        __syncthreads();
        unsigned cb = sbase + (it & 1) * STAGE_B;
        unsigned uAh = cb, uAl = cb + ARR_BYTES;
        unsigned uBh = cb + 2 * ARR_BYTES, uBl = cb + 3 * ARR_BYTES;
#pragma unroll
        for (int kk = 0; kk < 32; kk += 16) {
            unsigned bh[4][2], bl[4][2];
#pragma unroll
            for (int j2 = 0; j2 < 2; j2++) {
                unsigned bd = (unsigned)((boff + j2 * 16 * SMS + kk) * 2);
                LDSM4(bh[2 * j2][0], bh[2 * j2][1], bh[2 * j2 + 1][0],
                      bh[2 * j2 + 1][1], uBh + bd);
                LDSM4(bl[2 * j2][0], bl[2 * j2][1], bl[2 * j2 + 1][0],
                      bl[2 * j2 + 1][1], uBl + bd);
            }
#pragma unroll
            for (int i = 0; i < 4; i++) {
                unsigned ah[4], al[4];
                unsigned ad = (unsigned)((aoff + i * 16 * SMS + kk) * 2);
                LDSM4(ah[0], ah[1], ah[2], ah[3], uAh + ad);
                LDSM4(al[0], al[1], al[2], al[3], uAl + ad);
#pragma unroll
                for (int j = 0; j < 4; j++) {
                    MMA_BF16(acc[i][j], ah, bh[j]);
                    MMA_BF16(acc[i][j], ah, bl[j]);
                    MMA_BF16(acc[i][j], al, bh[j]);
                }
            }
        }
        __syncthreads();
        if (it + 2 < niter) {
            unsigned o = cb + sidx;
            int k0 = (it + 2) * 32;
            cp16(o, pAh + k0);
            cp16(o + 16, pAh + k0 + 8);
            cp16(o + ARR_BYTES, pAl + k0);
            cp16(o + ARR_BYTES + 16, pAl + k0 + 8);
            cp16(o + 2 * ARR_BYTES, pBh + k0);
            cp16(o + 2 * ARR_BYTES + 16, pBh + k0 + 8);
            cp16(o + 3 * ARR_BYTES, pBl + k0);
            cp16(o + 3 * ARR_BYTES + 16, pBl + k0 + 8);
        }
        CP_COMMIT();
    }
#pragma unroll
    for (int i = 0; i < 4; i++) {
        int r0 = bm + m0 + i * 16 + g8;
#pragma unroll
        for (int j = 0; j < 4; j++) {
            int col = bnc + n0 + j * 8 + tig * 2;
            *(float2*)(C + (size_t)r0 * ldc + col) =
                make_float2(acc[i][j][0], acc[i][j][1]);
            *(float2*)(C + (size_t)(r0 + 8) * ldc + col) =
                make_float2(acc[i][j][2], acc[i][j][3]);
        }
    }
}

// ------------------------- QKV fused GEMM ------------------------------------
__global__ __launch_bounds__(256, 2) void gemm_qkv() {
    int bx = blockIdx.x;
    const __nv_bfloat16 *Bh, *Bl;
    float* C;
    int ldc, bnw, bnc;
    if (bx < 16) {
        Bh = g_wqh; Bl = g_wql; C = g_q; ldc = HQ * D;
        bnw = bx * 128; bnc = bx * 128;
    } else if (bx == 16) {
        Bh = g_wkh; Bl = g_wkl; C = g_k; ldc = G * D; bnw = 0; bnc = 0;
    } else {
        Bh = g_wvh; Bl = g_wvl; C = g_v; ldc = G * D; bnw = 0; bnc = 0;
    }
    gemm_core(g_xh, g_xl, Bh, Bl, C, ldc, blockIdx.y * 128, bnw, bnc, HID);
}

// ------------------------- Wo GEMM --------------------------------------------
__global__ __launch_bounds__(256, 2) void gemm_out(float* __restrict__ C) {
    gemm_core(g_ath, g_atl, g_woh, g_wol, C, HID, blockIdx.y * 128,
              blockIdx.x * 128, blockIdx.x * 128, HID);
}

// ------------------------- gate = x @ Wgate^T --------------------------------
__global__ void gate_kernel(const float* __restrict__ x,
                            const float* __restrict__ Wg) {
    int t = blockIdx.x;
    int w = threadIdx.x >> 5, lane = threadIdx.x & 31;
    const float* xr = x + (size_t)t * HID;
    const float* wr = Wg + (size_t)w * HID;
    float acc = 0.f;
    for (int i = lane; i < HID; i += 32) acc += xr[i] * wr[i];
#pragma unroll
    for (int off = 16; off; off >>= 1)
        acc += __shfl_xor_sync(0xffffffffu, acc, off);
    if (!lane) g_gate[t * 3 + w] = acc;
}

// ------------------------- RoPE: table + q apply ------------------------------
__global__ void rope_table_kernel() {
    int idx = blockIdx.x * blockDim.x + threadIdx.x;
    int t = idx >> 5, d = idx & 31;
    double inv = exp(-(double)d * (log(10000.0) / 32.0));
    double sn, cs;
    sincos((double)t * inv, &sn, &cs);
    g_cos[t * 32 + d] = (float)cs;
    g_sin[t * 32 + d] = (float)sn;
}

__global__ void rope_apply_kernel(float* x, int nh) {
    int t = blockIdx.x;
    for (int idx = threadIdx.x; idx < nh * 32; idx += blockDim.x) {
        int hh = idx >> 5, d = idx & 31;
        float cs = g_cos[t * 32 + d], sn = g_sin[t * 32 + d];
        float* p = x + ((size_t)t * nh + hh) * D;
        float x1 = p[d], x2 = p[d + 32];
        p[d]      = x1 * cs - x2 * sn;
        p[d + 32] = x2 * cs + x1 * sn;
    }
}

// ------------------------- compression -> fragment-permuted bf16 -------------
__global__ __launch_bounds__(256) void compress_kernel(
    const float* __restrict__ Wck, const float* __restrict__ Wcv) {
    int c = blockIdx.x, g = blockIdx.y, which = blockIdx.z;
    const float* src = which ? g_v : g_k;
    const float* W = (which ? Wcv : Wck) + (size_t)g * 2048 * D;
    __shared__ float win[32 * 64];
    __shared__ float partial[4][64];
    int tid = threadIdx.x;
    for (int i = tid; i < 2048; i += 256) {
        int j = i >> 6, dd = i & 63;
        win[i] = src[((size_t)(16 * c + j) * G + g) * D + dd];
    }
    __syncthreads();
    int d = tid & 63, q = tid >> 6;
    float acc = 0.f;
    const float* Wp = W + (size_t)(q * 512) * D + d;
    const float* wp = win + q * 512;
#pragma unroll 8
    for (int f = 0; f < 512; f++) acc += wp[f] * Wp[(size_t)f * D];
    partial[q][d] = acc;
    __syncthreads();
    if (tid < 64) {
        float val = partial[0][tid] + partial[1][tid] + partial[2][tid] +
                    partial[3][tid];
        __nv_bfloat16 h = __float2bfloat16(val);
        __nv_bfloat16 lo = __float2bfloat16(val - __bfloat162float(h));
        if (which == 0) {
            int nd = (frag_perm(tid >> 1) << 1) + (tid & 1);
            size_t o = ((size_t)g * 128 + c) * 64 + nd;
            g_ckh[o] = h;
            g_ckl[o] = lo;
        } else {
            int pc = (c & ~63) + (frag_perm((c & 63) >> 1) << 1) + (c & 1);
            size_t o = ((size_t)g * 64 + tid) * 128 + pc;
            g_cvth[o] = h;
            g_cvtl[o] = lo;
        }
    }
}

// ------------------------- top-k select (device helper) ----------------------
__device__ __forceinline__ void do_select(int t, int g, int b, float sc) {
    int qb = t >> 6;
    bool causal = (b <= qb);
    bool forced = (b < 1) || ((qb - b < 2) && causal);
    float val = causal ? (forced ? INFINITY : sc) : -INFINITY;
    unsigned selbits = 0;
    for (int it = 0; it < TOPK; it++) {
        float rv = val; int ri = b;
#pragma unroll
        for (int off = 16; off; off >>= 1) {
            float ov = __shfl_xor_sync(0xffffffffu, rv, off);
            int oi = __shfl_xor_sync(0xffffffffu, ri, off);
            if (ov > rv || (ov == rv && oi < ri)) { rv = ov; ri = oi; }
        }
        if (rv == -INFINITY) break;
        selbits |= (1u << ri);
        if (b == ri) val = -INFINITY;
    }
    if (b == 0) g_sel[(size_t)g * T + t] = selbits;
}

// ------------------------- compressed attention (MMA) + psum + select --------
__global__ __launch_bounds__(256) void comp_attn_kernel() {
    int t = blockIdx.x, g = blockIdx.y;
    int tid = threadIdx.x;
    int warp = tid >> 5, lane = tid & 31;
    int g8 = lane >> 2, tig = lane & 3;
    int h = tid >> 4, m16 = tid & 15;

    __shared__ float sS[16][128];
    __shared__ float sp[16][128];
    __shared__ float spsum[128];

    int nc = (t >= 31) ? ((t - 31) >> 4) + 1 : 0;
    float gate0 = 1.f / (1.f + expf(-g_gate[t * 3 + 0]));
    float* out = g_att + ((size_t)t * HQ + g * HG) * D;

    if (nc == 0) {
        if (tid < 32) do_select(t, g, tid, 0.f);
        int d0 = m16 << 2;
        *(float4*)(out + h * D + d0) = make_float4(0.f, 0.f, 0.f, 0.f);
        return;
    }

    // q fragments hi/lo, pre-scaled by SCALE
    unsigned aqh[4][4], aql[4][4];
    {
        const float* qbase = g_q + ((size_t)t * HQ + g * HG) * D;
#pragma unroll
        for (int c = 0; c < 4; c++) {
            int d0 = c * 16 + 2 * tig;
            float2 v00 = *(const float2*)(qbase + g8 * D + d0);
            float2 v10 = *(const float2*)(qbase + (g8 + 8) * D + d0);
            float2 v01 = *(const float2*)(qbase + g8 * D + d0 + 8);
            float2 v11 = *(const float2*)(qbase + (g8 + 8) * D + d0 + 8);
            split2(v00.x * SCALE, v00.y * SCALE, aqh[c][0], aql[c][0]);
            split2(v10.x * SCALE, v10.y * SCALE, aqh[c][1], aql[c][1]);
            split2(v01.x * SCALE, v01.y * SCALE, aqh[c][2], aql[c][2]);
            split2(v11.x * SCALE, v11.y * SCALE, aqh[c][3], aql[c][3]);
        }
    }

    {
#pragma unroll
        for (int j = 0; j < 2; j++) {
            float S[4] = {0.f, 0.f, 0.f, 0.f};
            int crow = 16 * warp + 8 * j + g8;
            size_t rowoff = ((size_t)g * 128 + crow) * 64;
            const uint4* ph = (const uint4*)(g_ckh + rowoff) + tig * 2;
            const uint4* pl = (const uint4*)(g_ckl + rowoff) + tig * 2;
            uint4 H0 = ph[0], H1 = ph[1];
            uint4 L0 = pl[0], L1 = pl[1];
            unsigned bh[4][2] = {{H0.x, H0.y}, {H0.z, H0.w},
                                 {H1.x, H1.y}, {H1.z, H1.w}};
            unsigned bl[4][2] = {{L0.x, L0.y}, {L0.z, L0.w},
                                 {L1.x, L1.y}, {L1.z, L1.w}};
#pragma unroll
            for (int c4 = 0; c4 < 4; c4++) {
                MMA_BF16(S, aqh[c4], bh[c4]);
                MMA_BF16(S, aql[c4], bh[c4]);
                MMA_BF16(S, aqh[c4], bl[c4]);
            }
            int cc = 16 * warp + 8 * j + 2 * tig;
            sS[g8][cc] = S[0];
            sS[g8][cc + 1] = S[1];
            sS[g8 + 8][cc] = S[2];
            sS[g8 + 8][cc + 1] = S[3];
        }
    }
    __syncthreads();

    {
        float sv[8];
        float mx = -INFINITY;
#pragma unroll
        for (int r = 0; r < 8; r++) {
            int c = r * 16 + m16;
            float v = (c < nc) ? sS[h][c] : -INFINITY;
            sv[r] = v;
            mx = fmaxf(mx, v);
        }
#pragma unroll
        for (int off = 8; off; off >>= 1)
            mx = fmaxf(mx, __shfl_xor_sync(0xffffffffu, mx, off, 16));
        float l = 0.f;
#pragma unroll
        for (int r = 0; r < 8; r++) {
            sv[r] = __expf(sv[r] - mx);
            l += sv[r];
        }
#pragma unroll
        for (int off = 8; off; off >>= 1)
            l += __shfl_xor_sync(0xffffffffu, l, off, 16);
        float invl = 1.f / l;
#pragma unroll
        for (int r = 0; r < 8; r++) sp[h][r * 16 + m16] = sv[r] * invl;
    }
    __syncthreads();

    if (tid < 128) {
        float s = 0.f;
        if (tid < nc) {
#pragma unroll
            for (int hh = 0; hh < HG; hh++) s += sp[hh][tid];
        }
        spsum[tid] = s;
    }
    __syncthreads();

    // warp 0: embedded block-score + stable top-k (identical to old select)
    if (tid < 32) {
        int b = tid;
        float sc = 0.f;
        int clo = 4 * b - 1; if (clo < 0) clo = 0;
        int chi = 4 * b + 3; if (chi > C_NUM - 1) chi = C_NUM - 1;
        for (int c = clo; c <= chi; c++) sc += spsum[c];
        do_select(t, g, b, sc);
    }

    float acc[4] = {0.f, 0.f, 0.f, 0.f};
#pragma unroll
    for (int b64 = 0; b64 < 2; b64++) {
        size_t rowoff = ((size_t)g * 64 + 8 * warp + g8) * 128 + 64 * b64;
        const uint4* pvh = (const uint4*)(g_cvth + rowoff) + tig * 2;
        const uint4* pvl = (const uint4*)(g_cvtl + rowoff) + tig * 2;
        uint4 H0 = pvh[0], H1 = pvh[1];
        uint4 L0 = pvl[0], L1 = pvl[1];
        unsigned bh[4][2] = {{H0.x, H0.y}, {H0.z, H0.w},
                             {H1.x, H1.y}, {H1.z, H1.w}};
        unsigned bl[4][2] = {{L0.x, L0.y}, {L0.z, L0.w},
                             {L1.x, L1.y}, {L1.z, L1.w}};
#pragma unroll
        for (int kcl = 0; kcl < 4; kcl++) {
            int kc = 4 * b64 + kcl;
            float2 p00 = *(const float2*)&sp[g8][16 * kc + 2 * tig];
            float2 p10 = *(const float2*)&sp[g8 + 8][16 * kc + 2 * tig];
            float2 p01 = *(const float2*)&sp[g8][16 * kc + 8 + 2 * tig];
            float2 p11 = *(const float2*)&sp[g8 + 8][16 * kc + 8 + 2 * tig];
            unsigned ah[4], al[4];
            split2(p00.x, p00.y, ah[0], al[0]);
            split2(p10.x, p10.y, ah[1], al[1]);
            split2(p01.x, p01.y, ah[2], al[2]);
            split2(p11.x, p11.y, ah[3], al[3]);
            MMA_BF16(acc, ah, bh[kcl]);
            MMA_BF16(acc, al, bh[kcl]);
            MMA_BF16(acc, ah, bl[kcl]);
        }
    }
    int dcol = 8 * warp + 2 * tig;
    out[g8 * D + dcol] = gate0 * acc[0];
    out[g8 * D + dcol + 1] = gate0 * acc[1];
    out[(g8 + 8) * D + dcol] = gate0 * acc[2];
    out[(g8 + 8) * D + dcol + 1] = gate0 * acc[3];
}

// ------------------------- merged MMA flash attention ------------------------
// Union-block schedule; QK once per block; separate PV per branch (register
// budget: only one branch's P fragments live at a time).
__global__ __launch_bounds__(256) void attn_mma_kernel() {
    int t = blockIdx.x, g = blockIdx.y;
    int tid = threadIdx.x;
    int warp = tid >> 5, lane = tid & 31;
    int g8 = lane >> 2, tig = lane & 3;

    __shared__ float sm_m[8][16];
    __shared__ float sm_l[8][16];
    __shared__ float sacc[8][16][64];

    int qb = t >> 6;
    int lo = t - WINDOW; if (lo < 0) lo = 0;
    unsigned msel = g_sel[(size_t)g * T + t];
    unsigned mwin = ((2u << qb) - 1) & ~((1u << (lo >> 6)) - 1);
    unsigned mall = msel | mwin;

    // q fragments hi/lo, pre-scaled by SCALE
    unsigned aqh[4][4], aql[4][4];
    {
        const float* qbase = g_q + ((size_t)t * HQ + g * HG) * D;
#pragma unroll
        for (int c = 0; c < 4; c++) {
            int d0 = c * 16 + 2 * tig;
            float2 v00 = *(const float2*)(qbase + g8 * D + d0);
            float2 v10 = *(const float2*)(qbase + (g8 + 8) * D + d0);
            float2 v01 = *(const float2*)(qbase + g8 * D + d0 + 8);
            float2 v11 = *(const float2*)(qbase + (g8 + 8) * D + d0 + 8);
            split2(v00.x * SCALE, v00.y * SCALE, aqh[c][0], aql[c][0]);
            split2(v10.x * SCALE, v10.y * SCALE, aqh[c][1], aql[c][1]);
            split2(v01.x * SCALE, v01.y * SCALE, aqh[c][2], aql[c][2]);
            split2(v11.x * SCALE, v11.y * SCALE, aqh[c][3], aql[c][3]);
        }
    }

    float m1a = -INFINITY, m1b = -INFINITY, l1a = 0.f, l1b = 0.f;
    float m2a = -INFINITY, m2b = -INFINITY, l2a = 0.f, l2b = 0.f;
    float acc1[8][4], acc2[8][4];
#pragma unroll
    for (int j = 0; j < 8; j++)
#pragma unroll
        for (int r = 0; r < 4; r++) { acc1[j][r] = 0.f; acc2[j][r] = 0.f; }

    unsigned rem = mall;
    int bidx = 0;
    while (rem) {
        int b = __ffs(rem) - 1;
        rem &= rem - 1;
        if ((bidx++ & 7) != warp) continue;
        int sbase = b << 6;
        int smax = t - sbase; if (smax > 63) smax = 63;
        bool act1 = (msel >> b) & 1u;
        bool act2 = (mwin >> b) & 1u;
        int smin2 = lo - sbase; if (smin2 < 0) smin2 = 0;

        // ----- QK once (q pre-scaled) -----
        float S[8][4];
#pragma unroll
        for (int j = 0; j < 8; j++)
#pragma unroll
            for (int r = 0; r < 4; r++) S[j][r] = 0.f;
#pragma unroll
        for (int j = 0; j < 8; j++) {
            size_t rowoff = ((size_t)(sbase + 8 * j + g8) * G + g) * D;
            const uint4* ph = (const uint4*)(g_kh + rowoff) + tig * 2;
            const uint4* pl = (const uint4*)(g_kl + rowoff) + tig * 2;
            uint4 H0 = ph[0], H1 = ph[1];
            uint4 L0 = pl[0], L1 = pl[1];
            unsigned bh[4][2] = {{H0.x, H0.y}, {H0.z, H0.w},
                                 {H1.x, H1.y}, {H1.z, H1.w}};
            unsigned bl[4][2] = {{L0.x, L0.y}, {L0.z, L0.w},
                                 {L1.x, L1.y}, {L1.z, L1.w}};
#pragma unroll
            for (int c = 0; c < 4; c++) {
                MMA_BF16(S[j], aqh[c], bh[c]);
                MMA_BF16(S[j], aql[c], bh[c]);
                MMA_BF16(S[j], aqh[c], bl[c]);
            }
        }

        int soff = 2 * tig;

        // ----- branch 1: sparse (smin = 0) -----
        if (act1) {
            float bmax0 = -INFINITY, bmax1 = -INFINITY;
#pragma unroll
            for (int j = 0; j < 8; j++) {
                int s0i = 8 * j + soff, s1i = s0i + 1;
                if (s0i <= smax) {
                    bmax0 = fmaxf(bmax0, S[j][0]);
                    bmax1 = fmaxf(bmax1, S[j][2]);
                }
                if (s1i <= smax) {
                    bmax0 = fmaxf(bmax0, S[j][1]);
                    bmax1 = fmaxf(bmax1, S[j][3]);
                }
            }
            bmax0 = fmaxf(bmax0, __shfl_xor_sync(0xffffffffu, bmax0, 1));
            bmax0 = fmaxf(bmax0, __shfl_xor_sync(0xffffffffu, bmax0, 2));
            bmax1 = fmaxf(bmax1, __shfl_xor_sync(0xffffffffu, bmax1, 1));
            bmax1 = fmaxf(bmax1, __shfl_xor_sync(0xffffffffu, bmax1, 2));
            float mn0 = fmaxf(m1a, bmax0), mn1 = fmaxf(m1b, bmax1);
            float cor0 = __expf(m1a - mn0), cor1 = __expf(m1b - mn1);
            m1a = mn0; m1b = mn1;

            unsigned ph0[8], ph1[8], pl0[8], pl1[8];
            float ps0 = 0.f, ps1 = 0.f;
#pragma unroll
            for (int j = 0; j < 8; j++) {
                int s0i = 8 * j + soff, s1i = s0i + 1;
                float p0 = (s0i <= smax) ? __expf(S[j][0] - mn0) : 0.f;
                float p1 = (s1i <= smax) ? __expf(S[j][1] - mn0) : 0.f;
                float p2 = (s0i <= smax) ? __expf(S[j][2] - mn1) : 0.f;
                float p3 = (s1i <= smax) ? __expf(S[j][3] - mn1) : 0.f;
                ps0 += p0 + p1;
                ps1 += p2 + p3;
                split2(p0, p1, ph0[j], pl0[j]);
                split2(p2, p3, ph1[j], pl1[j]);
            }
            ps0 += __shfl_xor_sync(0xffffffffu, ps0, 1);
            ps0 += __shfl_xor_sync(0xffffffffu, ps0, 2);
            ps1 += __shfl_xor_sync(0xffffffffu, ps1, 1);
            ps1 += __shfl_xor_sync(0xffffffffu, ps1, 2);
            l1a = l1a * cor0 + ps0;
            l1b = l1b * cor1 + ps1;
#pragma unroll
            for (int j = 0; j < 8; j++) {
                acc1[j][0] *= cor0; acc1[j][1] *= cor0;
                acc1[j][2] *= cor1; acc1[j][3] *= cor1;
            }
#pragma unroll
            for (int jd = 0; jd < 8; jd++) {
                size_t rowoff = ((size_t)(g * D + g8 + 8 * jd)) * T + sbase;
                const uint4* pvh = (const uint4*)(g_vth + rowoff) + tig * 2;
                const uint4* pvl = (const uint4*)(g_vtl + rowoff) + tig * 2;
                uint4 H0 = pvh[0], H1 = pvh[1];
                uint4 L0 = pvl[0], L1 = pvl[1];
                unsigned bh[4][2] = {{H0.x, H0.y}, {H0.z, H0.w},
                                     {H1.x, H1.y}, {H1.z, H1.w}};
                unsigned bl[4][2] = {{L0.x, L0.y}, {L0.z, L0.w},
                                     {L1.x, L1.y}, {L1.z, L1.w}};
#pragma unroll
                for (int kc = 0; kc < 4; kc++) {
                    unsigned ah[4] = {ph0[2 * kc], ph1[2 * kc],
                                      ph0[2 * kc + 1], ph1[2 * kc + 1]};
                    unsigned al_[4] = {pl0[2 * kc], pl1[2 * kc],
                                       pl0[2 * kc + 1], pl1[2 * kc + 1]};
                    MMA_BF16(acc1[jd], ah, bh[kc]);
                    MMA_BF16(acc1[jd], al_, bh[kc]);
                    MMA_BF16(acc1[jd], ah, bl[kc]);
                }
            }
        }

        // ----- branch 2: sliding window [smin2, smax] -----
        if (act2) {
            float bmax0 = -INFINITY, bmax1 = -INFINITY;
#pragma unroll
            for (int j = 0; j < 8; j++) {
                int s0i = 8 * j + soff, s1i = s0i + 1;
                if (s0i >= smin2 && s0i <= smax) {
                    bmax0 = fmaxf(bmax0, S[j][0]);
                    bmax1 = fmaxf(bmax1, S[j][2]);
                }
                if (s1i >= smin2 && s1i <= smax) {
                    bmax0 = fmaxf(bmax0, S[j][1]);
                    bmax1 = fmaxf(bmax1, S[j][3]);
                }
            }
            bmax0 = fmaxf(bmax0, __shfl_xor_sync(0xffffffffu, bmax0, 1));
            bmax0 = fmaxf(bmax0, __shfl_xor_sync(0xffffffffu, bmax0, 2));
            bmax1 = fmaxf(bmax1, __shfl_xor_sync(0xffffffffu, bmax1, 1));
            bmax1 = fmaxf(bmax1, __shfl_xor_sync(0xffffffffu, bmax1, 2));
            float mn0 = fmaxf(m2a, bmax0), mn1 = fmaxf(m2b, bmax1);
            float cor0 = __expf(m2a - mn0), cor1 = __expf(m2b - mn1);
            m2a = mn0; m2b = mn1;

            unsigned ph0[8], ph1[8], pl0[8], pl1[8];
            float ps0 = 0.f, ps1 = 0.f;
#pragma unroll
            for (int j = 0; j < 8; j++) {
                int s0i = 8 * j + soff, s1i = s0i + 1;
                bool v0 = (s0i >= smin2) && (s0i <= smax);
                bool v1 = (s1i >= smin2) && (s1i <= smax);
                float p0 = v0 ? __expf(S[j][0] - mn0) : 0.f;
                float p1 = v1 ? __expf(S[j][1] - mn0) : 0.f;
                float p2 = v0 ? __expf(S[j][2] - mn1) : 0.f;
                float p3 = v1 ? __expf(S[j][3] - mn1) : 0.f;
                ps0 += p0 + p1;
                ps1 += p2 + p3;
                split2(p0, p1, ph0[j], pl0[j]);
                split2(p2, p3, ph1[j], pl1[j]);
            }
            ps0 += __shfl_xor_sync(0xffffffffu, ps0, 1);
            ps0 += __shfl_xor_sync(0xffffffffu, ps0, 2);
            ps1 += __shfl_xor_sync(0xffffffffu, ps1, 1);
            ps1 += __shfl_xor_sync(0xffffffffu, ps1, 2);
            l2a = l2a * cor0 + ps0;
            l2b = l2b * cor1 + ps1;
#pragma unroll
            for (int j = 0; j < 8; j++) {
                acc2[j][0] *= cor0; acc2[j][1] *= cor0;
                acc2[j][2] *= cor1; acc2[j][3] *= cor1;
            }
#pragma unroll
            for (int jd = 0; jd < 8; jd++) {
                size_t rowoff = ((size_t)(g * D + g8 + 8 * jd)) * T + sbase;
                const uint4* pvh = (const uint4*)(g_vth + rowoff) + tig * 2;
                const uint4* pvl = (const uint4*)(g_vtl + rowoff) + tig * 2;
                uint4 H0 = pvh[0], H1 = pvh[1];
                uint4 L0 = pvl[0], L1 = pvl[1];
                unsigned bh[4][2] = {{H0.x, H0.y}, {H0.z, H0.w},
                                     {H1.x, H1.y}, {H1.z, H1.w}};
                unsigned bl[4][2] = {{L0.x, L0.y}, {L0.z, L0.w},
                                     {L1.x, L1.y}, {L1.z, L1.w}};
#pragma unroll
                for (int kc = 0; kc < 4; kc++) {
                    unsigned ah[4] = {ph0[2 * kc], ph1[2 * kc],
                                      ph0[2 * kc + 1], ph1[2 * kc + 1]};
                    unsigned al_[4] = {pl0[2 * kc], pl1[2 * kc],
                                       pl0[2 * kc + 1], pl1[2 * kc + 1]};
                    MMA_BF16(acc2[jd], ah, bh[kc]);
                    MMA_BF16(acc2[jd], al_, bh[kc]);
                    MMA_BF16(acc2[jd], ah, bl[kc]);
                }
            }
        }
    }

    int row = tid >> 4, col = (tid & 15) << 2;

    // ----- phase 1: merge branch 1 -----
    if (tig == 0) {
        sm_m[warp][g8] = m1a; sm_m[warp][g8 + 8] = m1b;
        sm_l[warp][g8] = l1a; sm_l[warp][g8 + 8] = l1b;
    }
#pragma unroll
    for (int j = 0; j < 8; j++) {
        sacc[warp][g8][8 * j + 2 * tig] = acc1[j][0];
        sacc[warp][g8][8 * j + 2 * tig + 1] = acc1[j][1];
        sacc[warp][g8 + 8][8 * j + 2 * tig] = acc1[j][2];
        sacc[warp][g8 + 8][8 * j + 2 * tig + 1] = acc1[j][3];
    }
    __syncthreads();
    float M1 = sm_m[0][row];
#pragma unroll
    for (int w = 1; w < 8; w++) M1 = fmaxf(M1, sm_m[w][row]);
    float L1 = 0.f;
    float o1[4] = {0, 0, 0, 0};
#pragma unroll
    for (int w = 0; w < 8; w++) {
        float f1 = __expf(sm_m[w][row] - M1);
        L1 += f1 * sm_l[w][row];
        const float* a1 = &sacc[w][row][col];
#pragma unroll
        for (int e = 0; e < 4; e++) o1[e] += f1 * a1[e];
    }
    __syncthreads();

    // ----- phase 2: merge branch 2 -----
    if (tig == 0) {
        sm_m[warp][g8] = m2a; sm_m[warp][g8 + 8] = m2b;
        sm_l[warp][g8] = l2a; sm_l[warp][g8 + 8] = l2b;
    }
#pragma unroll
    for (int j = 0; j < 8; j++) {
        sacc[warp][g8][8 * j + 2 * tig] = acc2[j][0];
        sacc[warp][g8][8 * j + 2 * tig + 1] = acc2[j][1];
        sacc[warp][g8 + 8][8 * j + 2 * tig] = acc2[j][2];
        sacc[warp][g8 + 8][8 * j + 2 * tig + 1] = acc2[j][3];
    }
    __syncthreads();
    float M2 = sm_m[0][row];
#pragma unroll
    for (int w = 1; w < 8; w++) M2 = fmaxf(M2, sm_m[w][row]);
    float L2 = 0.f;
    float o2[4] = {0, 0, 0, 0};
#pragma unroll
    for (int w = 0; w < 8; w++) {
        float f2 = __expf(sm_m[w][row] - M2);
        L2 += f2 * sm_l[w][row];
        const float* a2 = &sacc[w][row][col];
#pragma unroll
        for (int e = 0; e < 4; e++) o2[e] += f2 * a2[e];
    }

    float gg1 = 1.f / (1.f + expf(-g_gate[t * 3 + 1]));
    float gg2 = 1.f / (1.f + expf(-g_gate[t * 3 + 2]));
    float w1 = gg1 / L1, w2 = gg2 / L2;
    size_t oidx = (size_t)t * HID + (g * HG + row) * D + col;
    const float* cur = g_att + oidx;
    float vx = cur[0] + w1 * o1[0] + w2 * o2[0];
    float vy = cur[1] + w1 * o1[1] + w2 * o2[1];
    float vz = cur[2] + w1 * o1[2] + w2 * o2[2];
    float vw = cur[3] + w1 * o1[3] + w2 * o2[3];
    unsigned h0, l0_, h1, l1_;
    split2(vx, vy, h0, l0_);
    split2(vz, vw, h1, l1_);
    unsigned* oph = (unsigned*)(g_ath + oidx);
    unsigned* opl = (unsigned*)(g_atl + oidx);
    oph[0] = h0; oph[1] = h1;
    opl[0] = l0_; opl[1] = l1_;
}

// ------------------------- launch --------------------------------------------
extern "C" void kernel_launch(void* const* d_in, const int* in_sizes, int n_in,
                              void* d_out, int out_size) {
    const float* x   = (const float*)d_in[0];
    const float* Wq  = (const float*)d_in[1];
    const float* Wk  = (const float*)d_in[2];
    const float* Wv  = (const float*)d_in[3];
    const float* Wo  = (const float*)d_in[4];
    const float* Wg  = (const float*)d_in[5];
    const float* Wck = (const float*)d_in[6];
    const float* Wcv = (const float*)d_in[7];
    float* out = (float*)d_out;

    float* pq;
    cudaGetSymbolAddress((void**)&pq, g_q);

    cudaFuncSetAttribute(gemm_qkv, cudaFuncAttributeMaxDynamicSharedMemorySize,
                         GEMM_SMEM2);
    cudaFuncSetAttribute(gemm_out, cudaFuncAttributeMaxDynamicSharedMemorySize,
                         GEMM_SMEM2);

    split_all_kernel<<<SPLIT_BLOCKS, 256>>>(x, Wq, Wk, Wv, Wo);
    rope_table_kernel<<<256, 256>>>();

    gemm_qkv<<<dim3(18, T / 128), 256, GEMM_SMEM2>>>();
    gate_kernel<<<T, 96>>>(x, Wg);
    rope_apply_kernel<<<T, 256>>>(pq, HQ);
    ropek_kvsplit_kernel<<<(T * G * 32) / 256, 256>>>();
    compress_kernel<<<dim3(C_NUM, G, 2), 256>>>(Wck, Wcv);
    comp_attn_kernel<<<dim3(T, G), 256>>>();
    attn_mma_kernel<<<dim3(T, G), 256>>>();

    gemm_out<<<dim3(HID / 128, T / 128), 256, GEMM_SMEM2>>>(out);
}